// round 1
// baseline (speedup 1.0000x reference)
#include <cuda_runtime.h>

#define HW (1024*1024)
#define NIMG 20

// ---------------- static device scratch (no allocations allowed) ----------------
__device__ float g_S1  [NIMG*HW];        // horizontal box sums of blown
__device__ float g_GL1 [NIMG*512*512];   // gaussian pyramid of L_comp
__device__ float g_GL2 [NIMG*256*256];
__device__ float g_GL3 [NIMG*128*128];
__device__ float g_GL4 [NIMG*64*64];
__device__ float g_GW1 [NIMG*512*512];   // gaussian pyramid of w
__device__ float g_GW2 [NIMG*256*256];
__device__ float g_GW3 [NIMG*128*128];
__device__ float g_GW4 [NIMG*64*64];
__device__ float g_LAP1[NIMG*512*512];   // laplacian levels 1..3
__device__ float g_LAP2[NIMG*256*256];
__device__ float g_LAP3[NIMG*128*128];
__device__ float g_P1  [4*512*512];      // collapse partials
__device__ float g_P2  [4*256*256];
__device__ float g_P3  [4*128*128];
__device__ float g_P4  [4*64*64];
__device__ float g_rowLsum[NIMG*1024];
__device__ float g_wpart [NIMG*128];
__device__ float g_Lm[NIMG];
__device__ float g_wm[NIMG];
__device__ float g_scale[NIMG];

// ---------------- K1: horizontal box (k=61) via block prefix scan + L row sums ----
__global__ void k_hbox(const float* __restrict__ L) {
    int row = blockIdx.x;
    int img = blockIdx.y;
    size_t base = ((size_t)img * 1024 + row) * 1024;
    const float4* src = reinterpret_cast<const float4*>(L + base);
    float4* dst = reinterpret_cast<float4*>(g_S1 + base);
    __shared__ float P[1024];
    __shared__ float woff[8];
    __shared__ float lred[8];
    int t = threadIdx.x;
    int lane = t & 31, wid = t >> 5;
    float4 v = src[t];
    float b0 = fmaxf(v.x - 0.88f, 0.f);
    float b1 = fmaxf(v.y - 0.88f, 0.f);
    float b2 = fmaxf(v.z - 0.88f, 0.f);
    float b3 = fmaxf(v.w - 0.88f, 0.f);
    float lsum = (v.x + v.y) + (v.z + v.w);
    float p0 = b0, p1 = p0 + b1, p2 = p1 + b2, p3 = p2 + b3;
    float sc = p3;
    #pragma unroll
    for (int o = 1; o < 32; o <<= 1) {
        float nb = __shfl_up_sync(0xffffffffu, sc, o);
        if (lane >= o) sc += nb;
    }
    if (lane == 31) woff[wid] = sc;
    #pragma unroll
    for (int o = 16; o; o >>= 1) lsum += __shfl_down_sync(0xffffffffu, lsum, o);
    if (lane == 0) lred[wid] = lsum;
    __syncthreads();
    if (t == 0) {
        float a = 0.f, ls = 0.f;
        #pragma unroll
        for (int i = 0; i < 8; i++) { float tmp = woff[i]; woff[i] = a; a += tmp; ls += lred[i]; }
        g_rowLsum[img * 1024 + row] = ls;
    }
    __syncthreads();
    float basep = woff[wid] + (sc - p3);
    P[4*t+0] = basep + p0;
    P[4*t+1] = basep + p1;
    P[4*t+2] = basep + p2;
    P[4*t+3] = basep + p3;
    __syncthreads();
    float4 o4;
    float* po = &o4.x;
    #pragma unroll
    for (int k = 0; k < 4; k++) {
        int xi = 4*t + k;
        int hi = min(xi + 30, 1023);
        int lo = xi - 31;
        po[k] = P[hi] - (lo >= 0 ? P[lo] : 0.f);
    }
    dst[t] = o4;
}

// ---------------- K2: vertical box + quality + w (fused) + w partial sums --------
__global__ void k_vbox(const float* __restrict__ L, float* __restrict__ wout) {
    int col = blockIdx.x * 64 + threadIdx.x;
    int ys = blockIdx.y * 128;
    int b = blockIdx.z;
    const float cb = -15.f / 3721.f;
    float s[5], wacc[5];
    const float *S1p[5], *Lp[5];
    float *Wp[5];
    #pragma unroll
    for (int n = 0; n < 5; n++) {
        size_t base = (size_t)(b*5+n) * HW + col;
        S1p[n] = g_S1 + base;
        Lp[n]  = L + base;
        Wp[n]  = wout + base;
        s[n] = 0.f; wacc[n] = 0.f;
    }
    for (int j = ys - 30; j <= ys + 30; j++) {
        if (j >= 0 && j < 1024) {
            size_t off = (size_t)j * 1024;
            #pragma unroll
            for (int n = 0; n < 5; n++) s[n] += S1p[n][off];
        }
    }
    for (int y = ys; y < ys + 128; y++) {
        size_t off = (size_t)y * 1024;
        float q[5];
        float qs = 1e-6f;
        #pragma unroll
        for (int n = 0; n < 5; n++) {
            float Lv = Lp[n][off];
            float u = 2.f*Lv - 1.f;
            float t1 = 1.f - u*u;
            float baseq = t1*t1;
            float sat  = 1.f/(1.f + __expf( 15.f*(Lv - 0.88f)));
            float dark = 1.f/(1.f + __expf(-25.f*(Lv - 0.04f)));
            float bloom = __expf(cb * s[n]);
            float qn = fmaxf(baseq*sat*dark*bloom, 0.02f);
            q[n] = qn; qs += qn;
        }
        float inv = 1.f/qs;
        #pragma unroll
        for (int n = 0; n < 5; n++) {
            float wv = q[n]*inv;
            Wp[n][off] = wv;
            wacc[n] += wv;
        }
        int ya = y + 31, yr = y - 30;
        #pragma unroll
        for (int n = 0; n < 5; n++) {
            float add = (ya < 1024) ? S1p[n][(size_t)ya*1024] : 0.f;
            float sub = (yr >= 0)  ? S1p[n][(size_t)yr*1024] : 0.f;
            s[n] += add - sub;
        }
    }
    __shared__ float red[64];
    for (int n = 0; n < 5; n++) {
        red[threadIdx.x] = wacc[n];
        __syncthreads();
        for (int o = 32; o; o >>= 1) {
            if (threadIdx.x < o) red[threadIdx.x] += red[threadIdx.x + o];
            __syncthreads();
        }
        if (threadIdx.x == 0)
            g_wpart[(b*5+n)*128 + blockIdx.y*16 + blockIdx.x] = red[0];
        __syncthreads();
    }
}

// ---------------- K3: per-(b,n) means, K3b: exposure scales ----------------------
__global__ void k_stats() {
    int bn = blockIdx.x;
    int t = threadIdx.x;
    float a = 0.f;
    for (int i = t; i < 1024; i += 256) a += g_rowLsum[bn*1024 + i];
    float wv = (t < 128) ? g_wpart[bn*128 + t] : 0.f;
    __shared__ float ra[256], rw[256];
    ra[t] = a; rw[t] = wv;
    __syncthreads();
    for (int o = 128; o; o >>= 1) {
        if (t < o) { ra[t] += ra[t+o]; rw[t] += rw[t+o]; }
        __syncthreads();
    }
    if (t == 0) {
        g_Lm[bn] = fmaxf(ra[0] * (1.f/1048576.f), 0.05f);
        g_wm[bn] = rw[0] * (1.f/1048576.f);
    }
}

__global__ void k_scale() {
    int b = threadIdx.x;
    if (b < 4) {
        float num = 0.f, den = 1e-6f;
        for (int n = 0; n < 5; n++) {
            num += g_Lm[b*5+n] * g_wm[b*5+n];
            den += g_wm[b*5+n];
        }
        float target = num / den;
        for (int n = 0; n < 5; n++)
            g_scale[b*5+n] = target / g_Lm[b*5+n];
    }
}

// ---------------- K5: fused 5x5 binomial blur + 2x2 avg-pool (6-tap stride 2) ----
template<bool SCALE>
__global__ void k_down(const float* __restrict__ in, float* __restrict__ out,
                       int Hi, int Wi) {
    __shared__ __align__(16) float tile[20][68];
    int x0 = blockIdx.x * 32;
    int y0 = blockIdx.y * 8;
    int img = blockIdx.z;
    int Ho = Hi >> 1, Wo = Wi >> 1;
    const float* src = in + (size_t)img * Hi * Wi;
    float sc = SCALE ? g_scale[img] : 1.f;
    int t = threadIdx.x;
    for (int idx = t; idx < 20*68; idx += 256) {
        int r = idx / 68, c = idx - r*68;
        int gy = 2*y0 - 2 + r;
        int gx = 2*x0 - 2 + c;
        float v = 0.f;
        if (gy >= 0 && gy < Hi && gx >= 0 && gx < Wi) {
            v = src[(size_t)gy * Wi + gx];
            if (SCALE) v = fminf(fmaxf(v * sc, 0.f), 1.f);
        }
        tile[r][c] = v;
    }
    __syncthreads();
    int tx = t & 31, ty = t >> 5;
    const float kk[6] = {1.f/32, 5.f/32, 10.f/32, 10.f/32, 5.f/32, 1.f/32};
    float acc = 0.f;
    #pragma unroll
    for (int i = 0; i < 6; i++) {
        const float* rowp = &tile[2*ty + i][2*tx];
        float2 a  = *(const float2*)(rowp);
        float2 bb = *(const float2*)(rowp + 2);
        float2 cc = *(const float2*)(rowp + 4);
        float rs = kk[0]*a.x + kk[1]*a.y + kk[2]*bb.x + kk[3]*bb.y + kk[4]*cc.x + kk[5]*cc.y;
        acc += kk[i] * rs;
    }
    out[(size_t)img * Ho * Wo + (size_t)(y0 + ty) * Wo + (x0 + tx)] = acc;
}

// ---------------- bilinear 2x upsample (half-pixel, edge-renormalized) -----------
__device__ __forceinline__ float up1(const float* __restrict__ s, int Hs, int Ws,
                                     int y, int x) {
    int iy = (y - 1) >> 1, ix = (x - 1) >> 1;
    float fy = (y & 1) ? 0.25f : 0.75f;
    float fx = (x & 1) ? 0.25f : 0.75f;
    int y0 = max(iy, 0), y1 = min(iy + 1, Hs - 1);
    int x0 = max(ix, 0), x1 = min(ix + 1, Ws - 1);
    float a = s[(size_t)y0*Ws + x0], b = s[(size_t)y0*Ws + x1];
    float c = s[(size_t)y1*Ws + x0], d = s[(size_t)y1*Ws + x1];
    float top = a + fx*(b - a);
    float bot = c + fx*(d - c);
    return top + fy*(bot - top);
}

// ---------------- K6: laplacian levels 1..3 --------------------------------------
__global__ void k_lap(const float* __restrict__ g, const float* __restrict__ gn,
                      float* __restrict__ lap, int H, int W) {
    int idx = blockIdx.x * 256 + threadIdx.x;
    int total = 20 * H * W;
    if (idx >= total) return;
    int img = idx / (H*W);
    int rem = idx - img*(H*W);
    int y = rem / W, x = rem - y*W;
    int Hn = H >> 1, Wn = W >> 1;
    lap[idx] = g[idx] - up1(gn + (size_t)img*Hn*Wn, Hn, Wn, y, x);
}

// ---------------- K7: blend top level, mid levels, final -------------------------
__global__ void k_blend4() {
    int idx = blockIdx.x*256 + threadIdx.x;
    if (idx >= 4*64*64) return;
    int b = idx >> 12;
    int rem = idx & 4095;
    float gw[5];
    float qs = 1e-6f;
    #pragma unroll
    for (int n = 0; n < 5; n++) {
        gw[n] = g_GW4[(size_t)(b*5+n)*4096 + rem];
        qs += gw[n];
    }
    float inv = 1.f/qs;
    float acc = 0.f;
    #pragma unroll
    for (int n = 0; n < 5; n++)
        acc += g_GL4[(size_t)(b*5+n)*4096 + rem] * gw[n] * inv;
    g_P4[idx] = acc;
}

__global__ void k_blend_mid(const float* __restrict__ lap, const float* __restrict__ gw,
                            const float* __restrict__ pin, float* __restrict__ pout,
                            int H, int W) {
    int idx = blockIdx.x*256 + threadIdx.x;
    int total = 4*H*W;
    if (idx >= total) return;
    int b = idx / (H*W);
    int rem = idx - b*(H*W);
    int y = rem / W, x = rem - y*W;
    int Hn = H>>1, Wn = W>>1;
    float wv[5]; float qs = 1e-6f;
    #pragma unroll
    for (int n = 0; n < 5; n++) {
        wv[n] = gw[(size_t)(b*5+n)*H*W + rem];
        qs += wv[n];
    }
    float inv = 1.f/qs;
    float acc = up1(pin + (size_t)b*Hn*Wn, Hn, Wn, y, x);
    #pragma unroll
    for (int n = 0; n < 5; n++)
        acc += lap[(size_t)(b*5+n)*H*W + rem] * wv[n] * inv;
    pout[idx] = acc;
}

// 4 horizontal pixels at once: cols {2m-1,2m,2m+1,2m+2} clamped
__device__ __forceinline__ float4 up4(const float* __restrict__ s, int Ws,
                                      int ry0, int ry1, float fy,
                                      int c0, int c1, int c2, int c3) {
    const float* r0 = s + (size_t)ry0*Ws;
    const float* r1 = s + (size_t)ry1*Ws;
    float a0=r0[c0], a1=r0[c1], a2=r0[c2], a3=r0[c3];
    float b0=r1[c0], b1=r1[c1], b2=r1[c2], b3=r1[c3];
    float h0a = a0 + 0.75f*(a1-a0);
    float h1a = a1 + 0.25f*(a2-a1);
    float h2a = a1 + 0.75f*(a2-a1);
    float h3a = a2 + 0.25f*(a3-a2);
    float h0b = b0 + 0.75f*(b1-b0);
    float h1b = b1 + 0.25f*(b2-b1);
    float h2b = b1 + 0.75f*(b2-b1);
    float h3b = b2 + 0.25f*(b3-b2);
    float4 r;
    r.x = h0a + fy*(h0b-h0a);
    r.y = h1a + fy*(h1b-h1a);
    r.z = h2a + fy*(h2b-h2a);
    r.w = h3a + fy*(h3b-h3a);
    return r;
}

__global__ void k_final(const float* __restrict__ L, const float* __restrict__ w,
                        float* __restrict__ out) {
    int idx = blockIdx.x*256 + threadIdx.x;   // 2^20 threads, 4 px each
    int m = idx & 255;
    int y = (idx >> 8) & 1023;
    int b = idx >> 18;
    int iy = (y - 1) >> 1;
    float fy = (y & 1) ? 0.25f : 0.75f;
    int ry0 = max(iy, 0), ry1 = min(iy + 1, 511);
    int c0 = max(2*m - 1, 0);
    int c1 = 2*m;
    int c2 = min(2*m + 1, 511);
    int c3 = min(2*m + 2, 511);
    size_t pixoff = (size_t)y*1024 + 4*m;
    float4 W5[5];
    float4 ws = make_float4(1e-6f, 1e-6f, 1e-6f, 1e-6f);
    #pragma unroll
    for (int n = 0; n < 5; n++) {
        float4 wn = *reinterpret_cast<const float4*>(w + (size_t)(b*5+n)*HW + pixoff);
        W5[n] = wn;
        ws.x += wn.x; ws.y += wn.y; ws.z += wn.z; ws.w += wn.w;
    }
    float4 inv = make_float4(1.f/ws.x, 1.f/ws.y, 1.f/ws.z, 1.f/ws.w);
    float4 acc = up4(g_P1 + (size_t)b*512*512, 512, ry0, ry1, fy, c0, c1, c2, c3);
    #pragma unroll
    for (int n = 0; n < 5; n++) {
        int bn = b*5+n;
        float4 Ln = *reinterpret_cast<const float4*>(L + (size_t)bn*HW + pixoff);
        float sc = g_scale[bn];
        float4 u = up4(g_GL1 + (size_t)bn*512*512, 512, ry0, ry1, fy, c0, c1, c2, c3);
        acc.x += (fminf(fmaxf(Ln.x*sc, 0.f), 1.f) - u.x) * W5[n].x * inv.x;
        acc.y += (fminf(fmaxf(Ln.y*sc, 0.f), 1.f) - u.y) * W5[n].y * inv.y;
        acc.z += (fminf(fmaxf(Ln.z*sc, 0.f), 1.f) - u.z) * W5[n].z * inv.z;
        acc.w += (fminf(fmaxf(Ln.w*sc, 0.f), 1.f) - u.w) * W5[n].w * inv.w;
    }
    acc.x = fminf(fmaxf(acc.x, 0.f), 1.f);
    acc.y = fminf(fmaxf(acc.y, 0.f), 1.f);
    acc.z = fminf(fmaxf(acc.z, 0.f), 1.f);
    acc.w = fminf(fmaxf(acc.w, 0.f), 1.f);
    *reinterpret_cast<float4*>(out + (size_t)b*HW + pixoff) = acc;
}

// ---------------- launcher -------------------------------------------------------
extern "C" void kernel_launch(void* const* d_in, const int* in_sizes, int n_in,
                              void* d_out, int out_size) {
    const float* L = (const float*)d_in[0];
    float* out = (float*)d_out;
    float* w = out + (size_t)4*HW;   // output layout: L_fused (4*HW) then w (20*HW)

    float *pGL1,*pGL2,*pGL3,*pGL4,*pGW1,*pGW2,*pGW3,*pGW4;
    float *pLAP1,*pLAP2,*pLAP3,*pP1,*pP2,*pP3,*pP4;
    cudaGetSymbolAddress((void**)&pGL1,  g_GL1);
    cudaGetSymbolAddress((void**)&pGL2,  g_GL2);
    cudaGetSymbolAddress((void**)&pGL3,  g_GL3);
    cudaGetSymbolAddress((void**)&pGL4,  g_GL4);
    cudaGetSymbolAddress((void**)&pGW1,  g_GW1);
    cudaGetSymbolAddress((void**)&pGW2,  g_GW2);
    cudaGetSymbolAddress((void**)&pGW3,  g_GW3);
    cudaGetSymbolAddress((void**)&pGW4,  g_GW4);
    cudaGetSymbolAddress((void**)&pLAP1, g_LAP1);
    cudaGetSymbolAddress((void**)&pLAP2, g_LAP2);
    cudaGetSymbolAddress((void**)&pLAP3, g_LAP3);
    cudaGetSymbolAddress((void**)&pP1,   g_P1);
    cudaGetSymbolAddress((void**)&pP2,   g_P2);
    cudaGetSymbolAddress((void**)&pP3,   g_P3);
    cudaGetSymbolAddress((void**)&pP4,   g_P4);

    // quality / weights / stats
    k_hbox<<<dim3(1024,20), 256>>>(L);
    k_vbox<<<dim3(16,8,4), 64>>>(L, w);
    k_stats<<<20, 256>>>();
    k_scale<<<1, 32>>>();

    // L_comp gaussian pyramid (scale applied inline at level 0)
    k_down<true ><<<dim3(16,64,20), 256>>>(L,    pGL1, 1024, 1024);
    k_down<false><<<dim3( 8,32,20), 256>>>(pGL1, pGL2,  512,  512);
    k_down<false><<<dim3( 4,16,20), 256>>>(pGL2, pGL3,  256,  256);
    k_down<false><<<dim3( 2, 8,20), 256>>>(pGL3, pGL4,  128,  128);

    // w gaussian pyramid
    k_down<false><<<dim3(16,64,20), 256>>>(w,    pGW1, 1024, 1024);
    k_down<false><<<dim3( 8,32,20), 256>>>(pGW1, pGW2,  512,  512);
    k_down<false><<<dim3( 4,16,20), 256>>>(pGW2, pGW3,  256,  256);
    k_down<false><<<dim3( 2, 8,20), 256>>>(pGW3, pGW4,  128,  128);

    // laplacian levels 1..3 (level 0 fused into k_final)
    k_lap<<<(20*512*512+255)/256, 256>>>(pGL1, pGL2, pLAP1, 512, 512);
    k_lap<<<(20*256*256+255)/256, 256>>>(pGL2, pGL3, pLAP2, 256, 256);
    k_lap<<<(20*128*128+255)/256, 256>>>(pGL3, pGL4, pLAP3, 128, 128);

    // blend + collapse
    k_blend4<<<(4*64*64+255)/256, 256>>>();
    k_blend_mid<<<(4*128*128+255)/256, 256>>>(pLAP3, pGW3, pP4, pP3, 128, 128);
    k_blend_mid<<<(4*256*256+255)/256, 256>>>(pLAP2, pGW2, pP3, pP2, 256, 256);
    k_blend_mid<<<(4*512*512+255)/256, 256>>>(pLAP1, pGW1, pP2, pP1, 512, 512);
    k_final<<<4096, 256>>>(L, w, out);
}

// round 3
// speedup vs baseline: 2.3602x; 2.3602x over previous
#include <cuda_runtime.h>

#define HW (1024*1024)
#define NIMG 20

// ---------------- static device scratch ----------------
__device__ float g_S1  [NIMG*HW];        // hbox sums -> in-place vertical strip prefix
__device__ float g_vp  [NIMG*16*1024];   // per-strip vertical offsets [img][strip][col]
__device__ float g_GL1 [NIMG*512*512];
__device__ float g_GL2 [NIMG*256*256];
__device__ float g_GL3 [NIMG*128*128];
__device__ float g_GL4 [NIMG*64*64];
__device__ float g_GW1 [NIMG*512*512];
__device__ float g_GW2 [NIMG*256*256];
__device__ float g_GW3 [NIMG*128*128];
__device__ float g_GW4 [NIMG*64*64];
__device__ float g_P1  [4*512*512];
__device__ float g_P2  [4*256*256];
__device__ float g_P3  [4*128*128];
__device__ float g_P4  [4*64*64];
__device__ float g_rowLsum[NIMG*1024];
__device__ float g_wpart [NIMG*4096];
__device__ float g_Lm[NIMG];
__device__ float g_wm[NIMG];
__device__ float g_scale[NIMG];

// ---------------- K1: horizontal box (k=61) via block prefix scan + L row sums ---
__global__ void k_hbox(const float* __restrict__ L) {
    int row = blockIdx.x;
    int img = blockIdx.y;
    size_t base = ((size_t)img * 1024 + row) * 1024;
    const float4* src = reinterpret_cast<const float4*>(L + base);
    float4* dst = reinterpret_cast<float4*>(g_S1 + base);
    __shared__ float P[1024];
    __shared__ float woff[8];
    __shared__ float lred[8];
    int t = threadIdx.x;
    int lane = t & 31, wid = t >> 5;
    float4 v = src[t];
    float b0 = fmaxf(v.x - 0.88f, 0.f);
    float b1 = fmaxf(v.y - 0.88f, 0.f);
    float b2 = fmaxf(v.z - 0.88f, 0.f);
    float b3 = fmaxf(v.w - 0.88f, 0.f);
    float lsum = (v.x + v.y) + (v.z + v.w);
    float p0 = b0, p1 = p0 + b1, p2 = p1 + b2, p3 = p2 + b3;
    float sc = p3;
    #pragma unroll
    for (int o = 1; o < 32; o <<= 1) {
        float nb = __shfl_up_sync(0xffffffffu, sc, o);
        if (lane >= o) sc += nb;
    }
    if (lane == 31) woff[wid] = sc;
    #pragma unroll
    for (int o = 16; o; o >>= 1) lsum += __shfl_down_sync(0xffffffffu, lsum, o);
    if (lane == 0) lred[wid] = lsum;
    __syncthreads();
    if (t == 0) {
        float a = 0.f, ls = 0.f;
        #pragma unroll
        for (int i = 0; i < 8; i++) { float tmp = woff[i]; woff[i] = a; a += tmp; ls += lred[i]; }
        g_rowLsum[img * 1024 + row] = ls;
    }
    __syncthreads();
    float basep = woff[wid] + (sc - p3);
    P[4*t+0] = basep + p0;
    P[4*t+1] = basep + p1;
    P[4*t+2] = basep + p2;
    P[4*t+3] = basep + p3;
    __syncthreads();
    float4 o4;
    float* po = &o4.x;
    #pragma unroll
    for (int k = 0; k < 4; k++) {
        int xi = 4*t + k;
        int hi = min(xi + 30, 1023);
        int lo = xi - 31;
        po[k] = P[hi] - (lo >= 0 ? P[lo] : 0.f);
    }
    dst[t] = o4;
}

// ---------------- K2a: vertical strip-local prefix (in place), strip totals ------
__global__ void k_vscan() {
    int col = blockIdx.x * 256 + threadIdx.x;
    int img = blockIdx.z;
    float* p = g_S1 + (size_t)img*HW + (size_t)blockIdx.y*64*1024 + col;
    float acc = 0.f;
    #pragma unroll
    for (int c = 0; c < 4; c++) {
        float v[16];
        #pragma unroll
        for (int i = 0; i < 16; i++) v[i] = p[(c*16+i)*1024];
        #pragma unroll
        for (int i = 0; i < 16; i++) { acc += v[i]; p[(c*16+i)*1024] = acc; }
    }
    g_vp[((size_t)img*16 + blockIdx.y)*1024 + col] = acc;
}

// ---------------- K2b: exclusive prefix over 16 strip totals per column ----------
__global__ void k_voff() {
    int idx = blockIdx.x*256 + threadIdx.x;   // 20480
    if (idx >= NIMG*1024) return;
    int img = idx >> 10, col = idx & 1023;
    float* p = g_vp + (size_t)img*16*1024 + col;
    float run = 0.f;
    #pragma unroll
    for (int s = 0; s < 16; s++) { float t = p[s*1024]; p[s*1024] = run; run += t; }
}

// ---------------- K2c: quality + w (fully parallel) + w partial sums -------------
__global__ void k_quality(const float* __restrict__ L, float* __restrict__ wout) {
    int x = blockIdx.x * 256 + threadIdx.x;
    int y = blockIdx.y;
    int b = blockIdx.z;
    int t = threadIdx.x;
    int lane = t & 31, wid = t >> 5;
    const float cb = -15.f / 3721.f;
    int ya = min(y + 30, 1023);
    int yb = y - 31;
    float q[5];
    float qs = 1e-6f;
    #pragma unroll
    for (int n = 0; n < 5; n++) {
        int img = b*5 + n;
        const float* S  = g_S1 + (size_t)img*HW;
        const float* vp = g_vp + (size_t)img*16*1024;
        float Va = S[(size_t)ya*1024 + x] + vp[(ya>>6)*1024 + x];
        float Vb = (yb >= 0) ? (S[(size_t)yb*1024 + x] + vp[(yb>>6)*1024 + x]) : 0.f;
        float Lv = L[(size_t)img*HW + (size_t)y*1024 + x];
        float u = 2.f*Lv - 1.f;
        float t1 = 1.f - u*u;
        float baseq = t1*t1;
        float sat  = 1.f/(1.f + __expf( 15.f*(Lv - 0.88f)));
        float dark = 1.f/(1.f + __expf(-25.f*(Lv - 0.04f)));
        float bloom = __expf(cb * (Va - Vb));
        float qn = fmaxf(baseq*sat*dark*bloom, 0.02f);
        q[n] = qn; qs += qn;
    }
    float inv = 1.f/qs;
    __shared__ float sred[5][8];
    #pragma unroll
    for (int n = 0; n < 5; n++) {
        float wv = q[n]*inv;
        wout[(size_t)(b*5+n)*HW + (size_t)y*1024 + x] = wv;
        #pragma unroll
        for (int o = 16; o; o >>= 1) wv += __shfl_down_sync(0xffffffffu, wv, o);
        if (lane == 0) sred[n][wid] = wv;
    }
    __syncthreads();
    if (t < 5) {
        float s = 0.f;
        #pragma unroll
        for (int i = 0; i < 8; i++) s += sred[t][i];
        g_wpart[(size_t)(b*5+t)*4096 + y*4 + blockIdx.x] = s;
    }
}

// ---------------- K3: per-(b,n) means, then scales -------------------------------
__global__ void k_stats() {
    int bn = blockIdx.x;
    int t = threadIdx.x;
    float a = 0.f;
    for (int i = t; i < 1024; i += 256) a += g_rowLsum[bn*1024 + i];
    float wv = 0.f;
    for (int i = t; i < 4096; i += 256) wv += g_wpart[(size_t)bn*4096 + i];
    __shared__ float ra[256], rw[256];
    ra[t] = a; rw[t] = wv;
    __syncthreads();
    for (int o = 128; o; o >>= 1) {
        if (t < o) { ra[t] += ra[t+o]; rw[t] += rw[t+o]; }
        __syncthreads();
    }
    if (t == 0) {
        g_Lm[bn] = fmaxf(ra[0] * (1.f/1048576.f), 0.05f);
        g_wm[bn] = rw[0] * (1.f/1048576.f);
    }
}

__global__ void k_scale() {
    int b = threadIdx.x;
    if (b < 4) {
        float num = 0.f, den = 1e-6f;
        for (int n = 0; n < 5; n++) {
            num += g_Lm[b*5+n] * g_wm[b*5+n];
            den += g_wm[b*5+n];
        }
        float target = num / den;
        for (int n = 0; n < 5; n++)
            g_scale[b*5+n] = target / g_Lm[b*5+n];
    }
}

// ---------------- K5: fused blur+pool downsample, L and w in one launch (z=40) ---
__global__ void k_down(const float* __restrict__ inA, const float* __restrict__ inB,
                       float* __restrict__ outA, float* __restrict__ outB,
                       int Hi, int Wi, int lvl0) {
    __shared__ __align__(16) float tile[20][68];
    int x0 = blockIdx.x * 32;
    int y0 = blockIdx.y * 8;
    int z = blockIdx.z;
    bool isA = z < NIMG;
    int img = isA ? z : z - NIMG;
    int Ho = Hi >> 1, Wo = Wi >> 1;
    const float* src = (isA ? inA : inB) + (size_t)img * Hi * Wi;
    float* dst = (isA ? outA : outB) + (size_t)img * Ho * Wo;
    bool doclip = lvl0 && isA;
    float sc = doclip ? g_scale[img] : 1.f;
    int t = threadIdx.x;
    for (int idx = t; idx < 20*68; idx += 256) {
        int r = idx / 68, c = idx - r*68;
        int gy = 2*y0 - 2 + r;
        int gx = 2*x0 - 2 + c;
        float v = 0.f;
        if (gy >= 0 && gy < Hi && gx >= 0 && gx < Wi) {
            v = src[(size_t)gy * Wi + gx];
            if (doclip) v = fminf(fmaxf(v * sc, 0.f), 1.f);
        }
        tile[r][c] = v;
    }
    __syncthreads();
    int tx = t & 31, ty = t >> 5;
    const float kk[6] = {1.f/32, 5.f/32, 10.f/32, 10.f/32, 5.f/32, 1.f/32};
    float acc = 0.f;
    #pragma unroll
    for (int i = 0; i < 6; i++) {
        const float* rowp = &tile[2*ty + i][2*tx];
        float2 a  = *(const float2*)(rowp);
        float2 bb = *(const float2*)(rowp + 2);
        float2 cc = *(const float2*)(rowp + 4);
        float rs = kk[0]*a.x + kk[1]*a.y + kk[2]*bb.x + kk[3]*bb.y + kk[4]*cc.x + kk[5]*cc.y;
        acc += kk[i] * rs;
    }
    dst[(size_t)(y0 + ty) * Wo + (x0 + tx)] = acc;
}

// ---------------- bilinear 2x upsample helper ------------------------------------
__device__ __forceinline__ float up1(const float* __restrict__ s, int Hs, int Ws,
                                     int y, int x) {
    int iy = (y - 1) >> 1, ix = (x - 1) >> 1;
    float fy = (y & 1) ? 0.25f : 0.75f;
    float fx = (x & 1) ? 0.25f : 0.75f;
    int y0 = max(iy, 0), y1 = min(iy + 1, Hs - 1);
    int x0 = max(ix, 0), x1 = min(ix + 1, Ws - 1);
    float a = s[(size_t)y0*Ws + x0], b = s[(size_t)y0*Ws + x1];
    float c = s[(size_t)y1*Ws + x0], d = s[(size_t)y1*Ws + x1];
    float top = a + fx*(b - a);
    float bot = c + fx*(d - c);
    return top + fy*(bot - top);
}

// ---------------- K6: top-level blend --------------------------------------------
__global__ void k_blend4() {
    int idx = blockIdx.x*256 + threadIdx.x;
    if (idx >= 4*64*64) return;
    int b = idx >> 12;
    int rem = idx & 4095;
    float gw[5];
    float qs = 1e-6f;
    #pragma unroll
    for (int n = 0; n < 5; n++) {
        gw[n] = g_GW4[(size_t)(b*5+n)*4096 + rem];
        qs += gw[n];
    }
    float inv = 1.f/qs;
    float acc = 0.f;
    #pragma unroll
    for (int n = 0; n < 5; n++)
        acc += g_GL4[(size_t)(b*5+n)*4096 + rem] * gw[n] * inv;
    g_P4[idx] = acc;
}

// ---------------- K7: mid blend with inline laplacian ----------------------------
__global__ void k_blend(const float* __restrict__ GL, const float* __restrict__ GLn,
                        const float* __restrict__ GW, const float* __restrict__ pin,
                        float* __restrict__ pout, int H, int W) {
    int idx = blockIdx.x*256 + threadIdx.x;
    int total = 4*H*W;
    if (idx >= total) return;
    int b = idx / (H*W);
    int rem = idx - b*(H*W);
    int y = rem / W, x = rem - y*W;
    int Hn = H>>1, Wn = W>>1;
    float wv[5]; float qs = 1e-6f;
    #pragma unroll
    for (int n = 0; n < 5; n++) {
        wv[n] = GW[(size_t)(b*5+n)*H*W + rem];
        qs += wv[n];
    }
    float inv = 1.f/qs;
    float acc = up1(pin + (size_t)b*Hn*Wn, Hn, Wn, y, x);
    #pragma unroll
    for (int n = 0; n < 5; n++) {
        float lap = GL[(size_t)(b*5+n)*H*W + rem]
                  - up1(GLn + (size_t)(b*5+n)*Hn*Wn, Hn, Wn, y, x);
        acc += lap * wv[n] * inv;
    }
    pout[idx] = acc;
}

// ---------------- K8: final — smem-tiled upsample + lap0 + blend + collapse ------
__global__ void k_final(const float* __restrict__ L, const float* __restrict__ w,
                        float* __restrict__ out) {
    __shared__ float sm[6][6][68];   // planes 0..4 = GL1 n, 5 = P1
    int s  = blockIdx.x;   // col tile (128 out px)
    int tY = blockIdx.y;   // row tile (8 out rows)
    int b  = blockIdx.z;
    int t  = threadIdx.x;
    int cbase = 64*s - 1;
    int rbase = 4*tY - 1;
    for (int idx = t; idx < 6*6*68; idx += 256) {
        int pl = idx / (6*68);
        int rem = idx - pl*6*68;
        int rr = rem / 68, cc = rem - rr*68;
        int rs = min(max(rbase + rr, 0), 511);
        int cs = min(max(cbase + cc, 0), 511);
        float v;
        if (pl < 5) v = g_GL1[((size_t)(b*5+pl)*512 + rs)*512 + cs];
        else        v = g_P1 [((size_t)b*512 + rs)*512 + cs];
        sm[pl][rr][cc] = v;
    }
    __syncthreads();
    int mm = t & 31;
    int r  = t >> 5;
    int y  = 8*tY + r;
    float fy = (r & 1) ? 0.25f : 0.75f;
    int rr0 = ((r - 1) >> 1) + 1;
    int rr1 = rr0 + 1;
    int jc = 2*mm;
    int xo = 128*s + 4*mm;
    size_t po = (size_t)y*1024 + xo;

    float4 acc, u[5];
    {
        #pragma unroll
        for (int pl = 0; pl < 6; pl++) {
            float a0 = sm[pl][rr0][jc],   a1 = sm[pl][rr0][jc+1];
            float a2 = sm[pl][rr0][jc+2], a3 = sm[pl][rr0][jc+3];
            float c0 = sm[pl][rr1][jc],   c1 = sm[pl][rr1][jc+1];
            float c2 = sm[pl][rr1][jc+2], c3 = sm[pl][rr1][jc+3];
            float h0a = a0 + 0.75f*(a1-a0);
            float h1a = a1 + 0.25f*(a2-a1);
            float h2a = a1 + 0.75f*(a2-a1);
            float h3a = a2 + 0.25f*(a3-a2);
            float h0b = c0 + 0.75f*(c1-c0);
            float h1b = c1 + 0.25f*(c2-c1);
            float h2b = c1 + 0.75f*(c2-c1);
            float h3b = c2 + 0.25f*(c3-c2);
            float4 rv;
            rv.x = h0a + fy*(h0b-h0a);
            rv.y = h1a + fy*(h1b-h1a);
            rv.z = h2a + fy*(h2b-h2a);
            rv.w = h3a + fy*(h3b-h3a);
            if (pl < 5) u[pl] = rv; else acc = rv;
        }
    }
    float4 W5[5];
    float4 ws = make_float4(1e-6f, 1e-6f, 1e-6f, 1e-6f);
    #pragma unroll
    for (int n = 0; n < 5; n++) {
        float4 wn = *reinterpret_cast<const float4*>(w + (size_t)(b*5+n)*HW + po);
        W5[n] = wn;
        ws.x += wn.x; ws.y += wn.y; ws.z += wn.z; ws.w += wn.w;
    }
    float4 inv = make_float4(1.f/ws.x, 1.f/ws.y, 1.f/ws.z, 1.f/ws.w);
    #pragma unroll
    for (int n = 0; n < 5; n++) {
        int bn = b*5+n;
        float4 Ln = *reinterpret_cast<const float4*>(L + (size_t)bn*HW + po);
        float scv = g_scale[bn];
        acc.x += (fminf(fmaxf(Ln.x*scv, 0.f), 1.f) - u[n].x) * W5[n].x * inv.x;
        acc.y += (fminf(fmaxf(Ln.y*scv, 0.f), 1.f) - u[n].y) * W5[n].y * inv.y;
        acc.z += (fminf(fmaxf(Ln.z*scv, 0.f), 1.f) - u[n].z) * W5[n].z * inv.z;
        acc.w += (fminf(fmaxf(Ln.w*scv, 0.f), 1.f) - u[n].w) * W5[n].w * inv.w;
    }
    acc.x = fminf(fmaxf(acc.x, 0.f), 1.f);
    acc.y = fminf(fmaxf(acc.y, 0.f), 1.f);
    acc.z = fminf(fmaxf(acc.z, 0.f), 1.f);
    acc.w = fminf(fmaxf(acc.w, 0.f), 1.f);
    *reinterpret_cast<float4*>(out + (size_t)b*HW + po) = acc;
}

// ---------------- launcher -------------------------------------------------------
extern "C" void kernel_launch(void* const* d_in, const int* in_sizes, int n_in,
                              void* d_out, int out_size) {
    const float* L = (const float*)d_in[0];
    float* out = (float*)d_out;
    float* w = out + (size_t)4*HW;

    float *pGL1,*pGL2,*pGL3,*pGL4,*pGW1,*pGW2,*pGW3,*pGW4,*pP1,*pP2,*pP3,*pP4;
    cudaGetSymbolAddress((void**)&pGL1, g_GL1);
    cudaGetSymbolAddress((void**)&pGL2, g_GL2);
    cudaGetSymbolAddress((void**)&pGL3, g_GL3);
    cudaGetSymbolAddress((void**)&pGL4, g_GL4);
    cudaGetSymbolAddress((void**)&pGW1, g_GW1);
    cudaGetSymbolAddress((void**)&pGW2, g_GW2);
    cudaGetSymbolAddress((void**)&pGW3, g_GW3);
    cudaGetSymbolAddress((void**)&pGW4, g_GW4);
    cudaGetSymbolAddress((void**)&pP1,  g_P1);
    cudaGetSymbolAddress((void**)&pP2,  g_P2);
    cudaGetSymbolAddress((void**)&pP3,  g_P3);
    cudaGetSymbolAddress((void**)&pP4,  g_P4);

    // quality / weights / stats
    k_hbox   <<<dim3(1024,20), 256>>>(L);
    k_vscan  <<<dim3(4,16,20), 256>>>();
    k_voff   <<<80, 256>>>();
    k_quality<<<dim3(4,1024,4), 256>>>(L, w);
    k_stats  <<<20, 256>>>();
    k_scale  <<<1, 32>>>();

    // gaussian pyramids (L with inline scale+clip at level 0; L and w fused, z=40)
    k_down<<<dim3(16,64,40), 256>>>(L,    w,    pGL1, pGW1, 1024, 1024, 1);
    k_down<<<dim3( 8,32,40), 256>>>(pGL1, pGW1, pGL2, pGW2,  512,  512, 0);
    k_down<<<dim3( 4,16,40), 256>>>(pGL2, pGW2, pGL3, pGW3,  256,  256, 0);
    k_down<<<dim3( 2, 8,40), 256>>>(pGL3, pGW3, pGL4, pGW4,  128,  128, 0);

    // blend + collapse (laplacians inline)
    k_blend4<<<64, 256>>>();
    k_blend<<<( 4*128*128+255)/256, 256>>>(pGL3, pGL4, pGW3, pP4, pP3, 128, 128);
    k_blend<<<( 4*256*256+255)/256, 256>>>(pGL2, pGL3, pGW2, pP3, pP2, 256, 256);
    k_blend<<<( 4*512*512+255)/256, 256>>>(pGL1, pGL2, pGW1, pP2, pP1, 512, 512);
    k_final<<<dim3(8,128,4), 256>>>(L, w, out);
}

// round 5
// speedup vs baseline: 2.5484x; 1.0798x over previous
#include <cuda_runtime.h>

#define HW (1024*1024)
#define NIMG 20

// ---------------- static device scratch ----------------
__device__ float g_S1  [NIMG*HW];        // hbox sums -> in-place vertical strip prefix
__device__ float g_vp  [NIMG*16*1024];   // per-strip vertical offsets [img][strip][col]
__device__ float g_GL1 [NIMG*512*512];
__device__ float g_GL2 [NIMG*256*256];
__device__ float g_GL3 [NIMG*128*128];
__device__ float g_GL4 [NIMG*64*64];
__device__ float g_GW1 [NIMG*512*512];
__device__ float g_GW2 [NIMG*256*256];
__device__ float g_GW3 [NIMG*128*128];
__device__ float g_GW4 [NIMG*64*64];
__device__ float g_P1  [4*512*512];
__device__ float g_P2  [4*256*256];
__device__ float g_P3  [4*128*128];
__device__ float g_rowLsum[NIMG*1024];
__device__ float g_wpart [NIMG*1024];
__device__ float g_scale[NIMG];

// ---------------- K1: horizontal box (k=61) via block prefix scan + L row sums ---
__global__ void k_hbox(const float* __restrict__ L) {
    int row = blockIdx.x;
    int img = blockIdx.y;
    size_t base = ((size_t)img * 1024 + row) * 1024;
    const float4* src = reinterpret_cast<const float4*>(L + base);
    float4* dst = reinterpret_cast<float4*>(g_S1 + base);
    __shared__ float P[1024];
    __shared__ float woff[8];
    __shared__ float lred[8];
    int t = threadIdx.x;
    int lane = t & 31, wid = t >> 5;
    float4 v = src[t];
    float b0 = fmaxf(v.x - 0.88f, 0.f);
    float b1 = fmaxf(v.y - 0.88f, 0.f);
    float b2 = fmaxf(v.z - 0.88f, 0.f);
    float b3 = fmaxf(v.w - 0.88f, 0.f);
    float lsum = (v.x + v.y) + (v.z + v.w);
    float p0 = b0, p1 = p0 + b1, p2 = p1 + b2, p3 = p2 + b3;
    float sc = p3;
    #pragma unroll
    for (int o = 1; o < 32; o <<= 1) {
        float nb = __shfl_up_sync(0xffffffffu, sc, o);
        if (lane >= o) sc += nb;
    }
    if (lane == 31) woff[wid] = sc;
    #pragma unroll
    for (int o = 16; o; o >>= 1) lsum += __shfl_down_sync(0xffffffffu, lsum, o);
    if (lane == 0) lred[wid] = lsum;
    __syncthreads();
    if (t == 0) {
        float a = 0.f, ls = 0.f;
        #pragma unroll
        for (int i = 0; i < 8; i++) { float tmp = woff[i]; woff[i] = a; a += tmp; ls += lred[i]; }
        g_rowLsum[img * 1024 + row] = ls;
    }
    __syncthreads();
    float basep = woff[wid] + (sc - p3);
    P[4*t+0] = basep + p0;
    P[4*t+1] = basep + p1;
    P[4*t+2] = basep + p2;
    P[4*t+3] = basep + p3;
    __syncthreads();
    float4 o4;
    float* po = &o4.x;
    #pragma unroll
    for (int k = 0; k < 4; k++) {
        int xi = 4*t + k;
        int hi = min(xi + 30, 1023);
        int lo = xi - 31;
        po[k] = P[hi] - (lo >= 0 ? P[lo] : 0.f);
    }
    dst[t] = o4;
}

// ---------------- K2a: vertical strip-local prefix (in place), strip totals ------
__global__ void k_vscan() {
    int col = blockIdx.x * 256 + threadIdx.x;
    int img = blockIdx.z;
    float* p = g_S1 + (size_t)img*HW + (size_t)blockIdx.y*64*1024 + col;
    float acc = 0.f;
    #pragma unroll
    for (int c = 0; c < 4; c++) {
        float v[16];
        #pragma unroll
        for (int i = 0; i < 16; i++) v[i] = p[(c*16+i)*1024];
        #pragma unroll
        for (int i = 0; i < 16; i++) { acc += v[i]; p[(c*16+i)*1024] = acc; }
    }
    g_vp[((size_t)img*16 + blockIdx.y)*1024 + col] = acc;
}

// ---------------- K2b: exclusive prefix over 16 strip totals per column ----------
__global__ void k_voff() {
    int idx = blockIdx.x*256 + threadIdx.x;   // 20480
    if (idx >= NIMG*1024) return;
    int img = idx >> 10, col = idx & 1023;
    float* p = g_vp + (size_t)img*16*1024 + col;
    float run = 0.f;
    #pragma unroll
    for (int s = 0; s < 16; s++) { float t = p[s*1024]; p[s*1024] = run; run += t; }
}

// ---------------- K2c: quality + w, float4 per thread ----------------------------
__device__ __forceinline__ float quality1(float Lv, float V) {
    const float cb = -15.f / 3721.f;
    float u = 2.f*Lv - 1.f;
    float t1 = 1.f - u*u;
    float baseq = t1*t1;
    float sat  = 1.f/(1.f + __expf( 15.f*(Lv - 0.88f)));
    float dark = 1.f/(1.f + __expf(-25.f*(Lv - 0.04f)));
    float bloom = __expf(cb * V);
    return fmaxf(baseq*sat*dark*bloom, 0.02f);
}

__global__ void __launch_bounds__(256) k_quality(const float* __restrict__ L,
                                                 float* __restrict__ wout) {
    int t = threadIdx.x;          // float4 index: 256 * 4 = 1024 px per row
    int y = blockIdx.x;
    int b = blockIdx.y;
    int lane = t & 31, wid = t >> 5;
    int ya = min(y + 30, 1023);
    int yb = y - 31;
    float4 q[5];
    float4 qs = make_float4(1e-6f, 1e-6f, 1e-6f, 1e-6f);
    #pragma unroll
    for (int n = 0; n < 5; n++) {
        int img = b*5 + n;
        const float* Sbase  = g_S1 + (size_t)img*HW;
        const float* vpbase = g_vp + (size_t)img*16*1024;
        float4 Sa = reinterpret_cast<const float4*>(Sbase + (size_t)ya*1024)[t];
        float4 va = reinterpret_cast<const float4*>(vpbase + (ya>>6)*1024)[t];
        float4 V;
        V.x = Sa.x + va.x; V.y = Sa.y + va.y; V.z = Sa.z + va.z; V.w = Sa.w + va.w;
        if (yb >= 0) {
            float4 Sb = reinterpret_cast<const float4*>(Sbase + (size_t)yb*1024)[t];
            float4 vb = reinterpret_cast<const float4*>(vpbase + (yb>>6)*1024)[t];
            V.x -= Sb.x + vb.x; V.y -= Sb.y + vb.y; V.z -= Sb.z + vb.z; V.w -= Sb.w + vb.w;
        }
        float4 Lv = reinterpret_cast<const float4*>(L + (size_t)img*HW + (size_t)y*1024)[t];
        float4 qn;
        qn.x = quality1(Lv.x, V.x);
        qn.y = quality1(Lv.y, V.y);
        qn.z = quality1(Lv.z, V.z);
        qn.w = quality1(Lv.w, V.w);
        q[n] = qn;
        qs.x += qn.x; qs.y += qn.y; qs.z += qn.z; qs.w += qn.w;
    }
    float4 inv = make_float4(1.f/qs.x, 1.f/qs.y, 1.f/qs.z, 1.f/qs.w);
    __shared__ float sred[5][8];
    #pragma unroll
    for (int n = 0; n < 5; n++) {
        float4 wv;
        wv.x = q[n].x*inv.x; wv.y = q[n].y*inv.y;
        wv.z = q[n].z*inv.z; wv.w = q[n].w*inv.w;
        reinterpret_cast<float4*>(wout + (size_t)(b*5+n)*HW + (size_t)y*1024)[t] = wv;
        float s = (wv.x + wv.y) + (wv.z + wv.w);
        #pragma unroll
        for (int o = 16; o; o >>= 1) s += __shfl_down_sync(0xffffffffu, s, o);
        if (lane == 0) sred[n][wid] = s;
    }
    __syncthreads();
    if (t < 5) {
        float s = 0.f;
        #pragma unroll
        for (int i = 0; i < 8; i++) s += sred[t][i];
        g_wpart[(size_t)(b*5+t)*1024 + y] = s;
    }
}

// ---------------- K3: means + exposure scales (merged) ---------------------------
__global__ void k_statscale() {
    int b = blockIdx.x;     // 4 blocks
    int t = threadIdx.x;    // 256
    __shared__ float red[256];
    __shared__ float Lm[5], wm[5];
    for (int n = 0; n < 5; n++) {
        int bn = b*5 + n;
        float a = 0.f;
        for (int i = t; i < 1024; i += 256) a += g_rowLsum[bn*1024 + i];
        red[t] = a; __syncthreads();
        for (int o = 128; o; o >>= 1) { if (t < o) red[t] += red[t+o]; __syncthreads(); }
        if (t == 0) Lm[n] = fmaxf(red[0] * (1.f/1048576.f), 0.05f);
        __syncthreads();
        float ww = 0.f;
        for (int i = t; i < 1024; i += 256) ww += g_wpart[bn*1024 + i];
        red[t] = ww; __syncthreads();
        for (int o = 128; o; o >>= 1) { if (t < o) red[t] += red[t+o]; __syncthreads(); }
        if (t == 0) wm[n] = red[0] * (1.f/1048576.f);
        __syncthreads();
    }
    if (t == 0) {
        float num = 0.f, den = 1e-6f;
        #pragma unroll
        for (int n = 0; n < 5; n++) { num += Lm[n]*wm[n]; den += wm[n]; }
        float target = num / den;
        #pragma unroll
        for (int n = 0; n < 5; n++) g_scale[b*5+n] = target / Lm[n];
    }
}

// ---------------- K5: fused blur+pool downsample, L and w in one launch (z=40) ---
__global__ void k_down(const float* __restrict__ inA, const float* __restrict__ inB,
                       float* __restrict__ outA, float* __restrict__ outB,
                       int Hi, int Wi, int lvl0) {
    __shared__ __align__(16) float tile[20][68];
    int x0 = blockIdx.x * 32;
    int y0 = blockIdx.y * 8;
    int z = blockIdx.z;
    bool isA = z < NIMG;
    int img = isA ? z : z - NIMG;
    int Ho = Hi >> 1, Wo = Wi >> 1;
    const float* src = (isA ? inA : inB) + (size_t)img * Hi * Wi;
    float* dst = (isA ? outA : outB) + (size_t)img * Ho * Wo;
    bool doclip = lvl0 && isA;
    float sc = doclip ? g_scale[img] : 1.f;
    int t = threadIdx.x;
    for (int idx = t; idx < 20*68; idx += 256) {
        int r = idx / 68, c = idx - r*68;
        int gy = 2*y0 - 2 + r;
        int gx = 2*x0 - 2 + c;
        float v = 0.f;
        if (gy >= 0 && gy < Hi && gx >= 0 && gx < Wi) {
            v = src[(size_t)gy * Wi + gx];
            if (doclip) v = fminf(fmaxf(v * sc, 0.f), 1.f);
        }
        tile[r][c] = v;
    }
    __syncthreads();
    int tx = t & 31, ty = t >> 5;
    const float kk[6] = {1.f/32, 5.f/32, 10.f/32, 10.f/32, 5.f/32, 1.f/32};
    float acc = 0.f;
    #pragma unroll
    for (int i = 0; i < 6; i++) {
        const float* rowp = &tile[2*ty + i][2*tx];
        float2 a  = *(const float2*)(rowp);
        float2 bb = *(const float2*)(rowp + 2);
        float2 cc = *(const float2*)(rowp + 4);
        float rs = kk[0]*a.x + kk[1]*a.y + kk[2]*bb.x + kk[3]*bb.y + kk[4]*cc.x + kk[5]*cc.y;
        acc += kk[i] * rs;
    }
    dst[(size_t)(y0 + ty) * Wo + (x0 + tx)] = acc;
}

// ---------------- bilinear 2x upsample helper ------------------------------------
__device__ __forceinline__ float up1(const float* __restrict__ s, int Hs, int Ws,
                                     int y, int x) {
    int iy = (y - 1) >> 1, ix = (x - 1) >> 1;
    float fy = (y & 1) ? 0.25f : 0.75f;
    float fx = (x & 1) ? 0.25f : 0.75f;
    int y0 = max(iy, 0), y1 = min(iy + 1, Hs - 1);
    int x0 = max(ix, 0), x1 = min(ix + 1, Ws - 1);
    float a = s[(size_t)y0*Ws + x0], b = s[(size_t)y0*Ws + x1];
    float c = s[(size_t)y1*Ws + x0], d = s[(size_t)y1*Ws + x1];
    float top = a + fx*(b - a);
    float bot = c + fx*(d - c);
    return top + fy*(bot - top);
}

// ---------------- K6: 128-level blend with inline P4 (blend4 folded in) ----------
__device__ __forceinline__ float p4at(int b, int j, int i) {
    float s = 1e-6f, a = 0.f;
    #pragma unroll
    for (int n = 0; n < 5; n++) {
        size_t o = (size_t)(b*5+n)*4096 + j*64 + i;
        float gw = g_GW4[o];
        s += gw;
        a += g_GL4[o] * gw;
    }
    return a / s;
}

__global__ void k_blend128() {
    int idx = blockIdx.x*256 + threadIdx.x;
    if (idx >= 4*128*128) return;
    int b = idx >> 14;
    int rem = idx & 16383;
    int y = rem >> 7, x = rem & 127;
    float wv[5]; float qs = 1e-6f;
    #pragma unroll
    for (int n = 0; n < 5; n++) {
        wv[n] = g_GW3[(size_t)(b*5+n)*16384 + rem];
        qs += wv[n];
    }
    float inv = 1.f/qs;
    // up1 of P4 computed inline
    int iy = (y - 1) >> 1, ix = (x - 1) >> 1;
    float fy = (y & 1) ? 0.25f : 0.75f;
    float fx = (x & 1) ? 0.25f : 0.75f;
    int y0 = max(iy, 0), y1 = min(iy + 1, 63);
    int x0 = max(ix, 0), x1 = min(ix + 1, 63);
    float a = p4at(b, y0, x0), bb = p4at(b, y0, x1);
    float c = p4at(b, y1, x0), d = p4at(b, y1, x1);
    float top = a + fx*(bb - a);
    float bot = c + fx*(d - c);
    float acc = top + fy*(bot - top);
    #pragma unroll
    for (int n = 0; n < 5; n++) {
        float lap = g_GL3[(size_t)(b*5+n)*16384 + rem]
                  - up1(g_GL4 + (size_t)(b*5+n)*4096, 64, 64, y, x);
        acc += lap * wv[n] * inv;
    }
    g_P3[idx] = acc;
}

// ---------------- K7: mid blend, 2 horizontal px per thread ----------------------
__global__ void k_blend2(const float* __restrict__ GL, const float* __restrict__ GLn,
                         const float* __restrict__ GW, const float* __restrict__ pin,
                         float* __restrict__ pout, int H, int W) {
    int idx = blockIdx.x*256 + threadIdx.x;
    int W2 = W >> 1;
    int total = 4*H*W2;
    if (idx >= total) return;
    int b = idx / (H*W2);
    int rem2 = idx - b*(H*W2);
    int y = rem2 / W2, i = rem2 - y*W2;     // output px pair (y, 2i) (y, 2i+1)
    int Hn = H>>1, Wn = W>>1;
    size_t rowoff = (size_t)y*W + 2*i;
    float2 wv[5]; float2 qs = make_float2(1e-6f, 1e-6f);
    #pragma unroll
    for (int n = 0; n < 5; n++) {
        float2 t = *reinterpret_cast<const float2*>(GW + (size_t)(b*5+n)*H*W + rowoff);
        wv[n] = t;
        qs.x += t.x; qs.y += t.y;
    }
    float2 inv = make_float2(1.f/qs.x, 1.f/qs.y);
    // shared vertical setup for the pair
    int iy = (y - 1) >> 1;
    float fy = (y & 1) ? 0.25f : 0.75f;
    int ry0 = max(iy, 0), ry1 = min(iy + 1, Hn - 1);
    int c0 = max(i - 1, 0);
    int c1 = i;
    int c2 = min(i + 1, Wn - 1);
    // pin upsample
    float2 acc;
    {
        const float* r0 = pin + (size_t)b*Hn*Wn + (size_t)ry0*Wn;
        const float* r1 = pin + (size_t)b*Hn*Wn + (size_t)ry1*Wn;
        float a0=r0[c0], a1=r0[c1], a2=r0[c2];
        float b0=r1[c0], b1=r1[c1], b2=r1[c2];
        float hx0 = a0 + 0.75f*(a1-a0), hx1 = a1 + 0.25f*(a2-a1);
        float gx0 = b0 + 0.75f*(b1-b0), gx1 = b1 + 0.25f*(b2-b1);
        acc.x = hx0 + fy*(gx0-hx0);
        acc.y = hx1 + fy*(gx1-hx1);
    }
    #pragma unroll
    for (int n = 0; n < 5; n++) {
        float2 gl = *reinterpret_cast<const float2*>(GL + (size_t)(b*5+n)*H*W + rowoff);
        const float* r0 = GLn + (size_t)(b*5+n)*Hn*Wn + (size_t)ry0*Wn;
        const float* r1 = GLn + (size_t)(b*5+n)*Hn*Wn + (size_t)ry1*Wn;
        float a0=r0[c0], a1=r0[c1], a2=r0[c2];
        float b0=r1[c0], b1=r1[c1], b2=r1[c2];
        float hx0 = a0 + 0.75f*(a1-a0), hx1 = a1 + 0.25f*(a2-a1);
        float gx0 = b0 + 0.75f*(b1-b0), gx1 = b1 + 0.25f*(b2-b1);
        float u0 = hx0 + fy*(gx0-hx0);
        float u1 = hx1 + fy*(gx1-hx1);
        acc.x += (gl.x - u0) * wv[n].x * inv.x;
        acc.y += (gl.y - u1) * wv[n].y * inv.y;
    }
    *reinterpret_cast<float2*>(pout + (size_t)b*H*W + rowoff) = acc;
}

// ---------------- K8: final — smem-tiled upsample + lap0 + blend + collapse ------
__global__ void k_final(const float* __restrict__ L, const float* __restrict__ w,
                        float* __restrict__ out) {
    __shared__ float sm[6][6][68];   // planes 0..4 = GL1 n, 5 = P1
    int s  = blockIdx.x;   // col tile (128 out px)
    int tY = blockIdx.y;   // row tile (8 out rows)
    int b  = blockIdx.z;
    int t  = threadIdx.x;
    int cbase = 64*s - 1;
    int rbase = 4*tY - 1;
    for (int idx = t; idx < 6*6*68; idx += 256) {
        int pl = idx / (6*68);
        int rem = idx - pl*6*68;
        int rr = rem / 68, cc = rem - rr*68;
        int rs = min(max(rbase + rr, 0), 511);
        int cs = min(max(cbase + cc, 0), 511);
        float v;
        if (pl < 5) v = g_GL1[((size_t)(b*5+pl)*512 + rs)*512 + cs];
        else        v = g_P1 [((size_t)b*512 + rs)*512 + cs];
        sm[pl][rr][cc] = v;
    }
    __syncthreads();
    int mm = t & 31;
    int r  = t >> 5;
    int y  = 8*tY + r;
    float fy = (r & 1) ? 0.25f : 0.75f;
    int rr0 = ((r - 1) >> 1) + 1;
    int rr1 = rr0 + 1;
    int jc = 2*mm;
    int xo = 128*s + 4*mm;
    size_t po = (size_t)y*1024 + xo;

    float4 acc, u[5];
    {
        #pragma unroll
        for (int pl = 0; pl < 6; pl++) {
            float a0 = sm[pl][rr0][jc],   a1 = sm[pl][rr0][jc+1];
            float a2 = sm[pl][rr0][jc+2], a3 = sm[pl][rr0][jc+3];
            float c0 = sm[pl][rr1][jc],   c1 = sm[pl][rr1][jc+1];
            float c2 = sm[pl][rr1][jc+2], c3 = sm[pl][rr1][jc+3];
            float h0a = a0 + 0.75f*(a1-a0);
            float h1a = a1 + 0.25f*(a2-a1);
            float h2a = a1 + 0.75f*(a2-a1);
            float h3a = a2 + 0.25f*(a3-a2);
            float h0b = c0 + 0.75f*(c1-c0);
            float h1b = c1 + 0.25f*(c2-c1);
            float h2b = c1 + 0.75f*(c2-c1);
            float h3b = c2 + 0.25f*(c3-c2);
            float4 rv;
            rv.x = h0a + fy*(h0b-h0a);
            rv.y = h1a + fy*(h1b-h1a);
            rv.z = h2a + fy*(h2b-h2a);
            rv.w = h3a + fy*(h3b-h3a);
            if (pl < 5) u[pl] = rv; else acc = rv;
        }
    }
    float4 W5[5];
    float4 ws = make_float4(1e-6f, 1e-6f, 1e-6f, 1e-6f);
    #pragma unroll
    for (int n = 0; n < 5; n++) {
        float4 wn = *reinterpret_cast<const float4*>(w + (size_t)(b*5+n)*HW + po);
        W5[n] = wn;
        ws.x += wn.x; ws.y += wn.y; ws.z += wn.z; ws.w += wn.w;
    }
    float4 inv = make_float4(1.f/ws.x, 1.f/ws.y, 1.f/ws.z, 1.f/ws.w);
    #pragma unroll
    for (int n = 0; n < 5; n++) {
        int bn = b*5+n;
        float4 Ln = *reinterpret_cast<const float4*>(L + (size_t)bn*HW + po);
        float scv = g_scale[bn];
        acc.x += (fminf(fmaxf(Ln.x*scv, 0.f), 1.f) - u[n].x) * W5[n].x * inv.x;
        acc.y += (fminf(fmaxf(Ln.y*scv, 0.f), 1.f) - u[n].y) * W5[n].y * inv.y;
        acc.z += (fminf(fmaxf(Ln.z*scv, 0.f), 1.f) - u[n].z) * W5[n].z * inv.z;
        acc.w += (fminf(fmaxf(Ln.w*scv, 0.f), 1.f) - u[n].w) * W5[n].w * inv.w;
    }
    acc.x = fminf(fmaxf(acc.x, 0.f), 1.f);
    acc.y = fminf(fmaxf(acc.y, 0.f), 1.f);
    acc.z = fminf(fmaxf(acc.z, 0.f), 1.f);
    acc.w = fminf(fmaxf(acc.w, 0.f), 1.f);
    *reinterpret_cast<float4*>(out + (size_t)b*HW + po) = acc;
}

// ---------------- launcher -------------------------------------------------------
extern "C" void kernel_launch(void* const* d_in, const int* in_sizes, int n_in,
                              void* d_out, int out_size) {
    const float* L = (const float*)d_in[0];
    float* out = (float*)d_out;
    float* w = out + (size_t)4*HW;

    float *pGL1,*pGL2,*pGL3,*pGL4,*pGW1,*pGW2,*pGW3,*pGW4,*pP1,*pP2,*pP3;
    cudaGetSymbolAddress((void**)&pGL1, g_GL1);
    cudaGetSymbolAddress((void**)&pGL2, g_GL2);
    cudaGetSymbolAddress((void**)&pGL3, g_GL3);
    cudaGetSymbolAddress((void**)&pGL4, g_GL4);
    cudaGetSymbolAddress((void**)&pGW1, g_GW1);
    cudaGetSymbolAddress((void**)&pGW2, g_GW2);
    cudaGetSymbolAddress((void**)&pGW3, g_GW3);
    cudaGetSymbolAddress((void**)&pGW4, g_GW4);
    cudaGetSymbolAddress((void**)&pP1,  g_P1);
    cudaGetSymbolAddress((void**)&pP2,  g_P2);
    cudaGetSymbolAddress((void**)&pP3,  g_P3);

    // quality / weights / stats
    k_hbox     <<<dim3(1024,20), 256>>>(L);
    k_vscan    <<<dim3(4,16,20), 256>>>();
    k_voff     <<<80, 256>>>();
    k_quality  <<<dim3(1024,4), 256>>>(L, w);
    k_statscale<<<4, 256>>>();

    // gaussian pyramids (L with inline scale+clip at level 0; L and w fused, z=40)
    k_down<<<dim3(16,64,40), 256>>>(L,    w,    pGL1, pGW1, 1024, 1024, 1);
    k_down<<<dim3( 8,32,40), 256>>>(pGL1, pGW1, pGL2, pGW2,  512,  512, 0);
    k_down<<<dim3( 4,16,40), 256>>>(pGL2, pGW2, pGL3, pGW3,  256,  256, 0);
    k_down<<<dim3( 2, 8,40), 256>>>(pGL3, pGW3, pGL4, pGW4,  128,  128, 0);

    // blend + collapse (laplacians inline; top blend folded into 128-level)
    k_blend128<<<(4*128*128+255)/256, 256>>>();
    k_blend2<<<(4*256*128+255)/256, 256>>>(pGL2, pGL3, pGW2, pP3, pP2, 256, 256);
    k_blend2<<<(4*512*256+255)/256, 256>>>(pGL1, pGL2, pGW1, pP2, pP1, 512, 512);
    k_final<<<dim3(8,128,4), 256>>>(L, w, out);
}

// round 8
// speedup vs baseline: 2.7058x; 1.0617x over previous
#include <cuda_runtime.h>

#define HW (1024*1024)
#define NIMG 20

// ---------------- static device scratch ----------------
__device__ float g_S1  [NIMG*HW];        // vertical strip-local prefix of hbox sums
__device__ float g_vp  [NIMG*32*1024];   // per-strip vertical offsets [img][strip][col]
__device__ float g_GL1 [NIMG*512*512];
__device__ float g_GL2 [NIMG*256*256];
__device__ float g_GL3 [NIMG*128*128];
__device__ float g_GL4 [NIMG*64*64];
__device__ float g_GW1 [NIMG*512*512];
__device__ float g_GW2 [NIMG*256*256];
__device__ float g_GW3 [NIMG*128*128];
__device__ float g_GW4 [NIMG*64*64];
__device__ float g_P1  [4*512*512];
__device__ float g_P2  [4*256*256];
__device__ float g_P3  [4*128*128];
__device__ float g_Lpart [NIMG*32];
__device__ float g_wpart [NIMG*1024];
__device__ float g_scale[NIMG];

// ---- K1: fused horizontal box (k=61, row prefix) + vertical strip prefix --------
// One block = one 32-row strip of one image. Horizontal prefix per row in smem
// (double buffered), vertical running sum held in registers, S1 written ONCE.
__global__ void __launch_bounds__(256) k_hvscan(const float* __restrict__ L) {
    int strip = blockIdx.x;            // 0..31
    int img   = blockIdx.y;            // 0..19
    int t = threadIdx.x;
    int lane = t & 31, wid = t >> 5;
    __shared__ float P[2][1024];
    __shared__ float woff[2][8];
    __shared__ float lred[8];
    float v0 = 0.f, v1 = 0.f, v2 = 0.f, v3 = 0.f;   // vertical running sums (4 cols)
    float lacc = 0.f;
    size_t base = ((size_t)img * 1024 + strip * 32) * 1024;
    const float4* src = reinterpret_cast<const float4*>(L + base);
    float4* dst = reinterpret_cast<float4*>(g_S1 + base);

    for (int r = 0; r < 32; r++) {
        int pp = r & 1;
        float4 v = src[r * 256 + t];
        lacc += (v.x + v.y) + (v.z + v.w);
        float b0 = fmaxf(v.x - 0.88f, 0.f);
        float b1 = fmaxf(v.y - 0.88f, 0.f);
        float b2 = fmaxf(v.z - 0.88f, 0.f);
        float b3 = fmaxf(v.w - 0.88f, 0.f);
        float p0 = b0, p1 = p0 + b1, p2 = p1 + b2, p3 = p2 + b3;
        float sc = p3;
        #pragma unroll
        for (int o = 1; o < 32; o <<= 1) {
            float nb = __shfl_up_sync(0xffffffffu, sc, o);
            if (lane >= o) sc += nb;
        }
        if (lane == 31) woff[pp][wid] = sc;
        __syncthreads();
        if (t == 0) {
            float a = 0.f;
            #pragma unroll
            for (int i = 0; i < 8; i++) { float tmp = woff[pp][i]; woff[pp][i] = a; a += tmp; }
        }
        __syncthreads();
        float bs = woff[pp][wid] + (sc - p3);
        P[pp][4*t+0] = bs + p0;
        P[pp][4*t+1] = bs + p1;
        P[pp][4*t+2] = bs + p2;
        P[pp][4*t+3] = bs + p3;
        __syncthreads();
        float4 o4;
        {
            int xi = 4*t;
            int hi0 = min(xi + 30, 1023), lo0 = xi - 31;
            float h0 = P[pp][hi0] - (lo0 >= 0 ? P[pp][lo0] : 0.f);
            int hi1 = min(xi + 31, 1023), lo1 = xi - 30;
            float h1 = P[pp][hi1] - (lo1 >= 0 ? P[pp][lo1] : 0.f);
            int hi2 = min(xi + 32, 1023), lo2 = xi - 29;
            float h2 = P[pp][hi2] - (lo2 >= 0 ? P[pp][lo2] : 0.f);
            int hi3 = min(xi + 33, 1023), lo3 = xi - 28;
            float h3 = P[pp][hi3] - (lo3 >= 0 ? P[pp][lo3] : 0.f);
            v0 += h0; v1 += h1; v2 += h2; v3 += h3;
            o4.x = v0; o4.y = v1; o4.z = v2; o4.w = v3;
        }
        dst[r * 256 + t] = o4;
    }
    // strip totals per column -> g_vp
    float4* vpd = reinterpret_cast<float4*>(g_vp + ((size_t)img*32 + strip)*1024);
    float4 tot; tot.x = v0; tot.y = v1; tot.z = v2; tot.w = v3;
    vpd[t] = tot;
    // strip L partial
    #pragma unroll
    for (int o = 16; o; o >>= 1) lacc += __shfl_down_sync(0xffffffffu, lacc, o);
    if (lane == 0) lred[wid] = lacc;
    __syncthreads();
    if (t == 0) {
        float s = 0.f;
        #pragma unroll
        for (int i = 0; i < 8; i++) s += lred[i];
        g_Lpart[img*32 + strip] = s;
    }
}

// ---------------- K2b: exclusive prefix over 32 strip totals per column ----------
__global__ void k_voff() {
    int idx = blockIdx.x*256 + threadIdx.x;   // 20480
    if (idx >= NIMG*1024) return;
    int img = idx >> 10, col = idx & 1023;
    float* p = g_vp + (size_t)img*32*1024 + col;
    float run = 0.f;
    #pragma unroll
    for (int s = 0; s < 32; s++) { float t = p[s*1024]; p[s*1024] = run; run += t; }
}

// ---------------- K2c: quality + w, float4 per thread ----------------------------
__device__ __forceinline__ float quality1(float Lv, float V) {
    const float cb = -15.f / 3721.f;
    float u = 2.f*Lv - 1.f;
    float t1 = 1.f - u*u;
    float baseq = t1*t1;
    float sat  = 1.f/(1.f + __expf( 15.f*(Lv - 0.88f)));
    float dark = 1.f/(1.f + __expf(-25.f*(Lv - 0.04f)));
    float bloom = __expf(cb * V);
    return fmaxf(baseq*sat*dark*bloom, 0.02f);
}

__global__ void __launch_bounds__(256) k_quality(const float* __restrict__ L,
                                                 float* __restrict__ wout) {
    int t = threadIdx.x;          // float4 index: 256 * 4 = 1024 px per row
    int y = blockIdx.x;
    int b = blockIdx.y;
    int lane = t & 31, wid = t >> 5;
    int ya = min(y + 30, 1023);
    int yb = y - 31;
    float4 q[5];
    float4 qs = make_float4(1e-6f, 1e-6f, 1e-6f, 1e-6f);
    #pragma unroll
    for (int n = 0; n < 5; n++) {
        int img = b*5 + n;
        const float* Sbase  = g_S1 + (size_t)img*HW;
        const float* vpbase = g_vp + (size_t)img*32*1024;
        float4 Sa = reinterpret_cast<const float4*>(Sbase + (size_t)ya*1024)[t];
        float4 va = reinterpret_cast<const float4*>(vpbase + (ya>>5)*1024)[t];
        float4 V;
        V.x = Sa.x + va.x; V.y = Sa.y + va.y; V.z = Sa.z + va.z; V.w = Sa.w + va.w;
        if (yb >= 0) {
            float4 Sb = reinterpret_cast<const float4*>(Sbase + (size_t)yb*1024)[t];
            float4 vb = reinterpret_cast<const float4*>(vpbase + (yb>>5)*1024)[t];
            V.x -= Sb.x + vb.x; V.y -= Sb.y + vb.y; V.z -= Sb.z + vb.z; V.w -= Sb.w + vb.w;
        }
        float4 Lv = reinterpret_cast<const float4*>(L + (size_t)img*HW + (size_t)y*1024)[t];
        float4 qn;
        qn.x = quality1(Lv.x, V.x);
        qn.y = quality1(Lv.y, V.y);
        qn.z = quality1(Lv.z, V.z);
        qn.w = quality1(Lv.w, V.w);
        q[n] = qn;
        qs.x += qn.x; qs.y += qn.y; qs.z += qn.z; qs.w += qn.w;
    }
    float4 inv = make_float4(1.f/qs.x, 1.f/qs.y, 1.f/qs.z, 1.f/qs.w);
    __shared__ float sred[5][8];
    #pragma unroll
    for (int n = 0; n < 5; n++) {
        float4 wv;
        wv.x = q[n].x*inv.x; wv.y = q[n].y*inv.y;
        wv.z = q[n].z*inv.z; wv.w = q[n].w*inv.w;
        reinterpret_cast<float4*>(wout + (size_t)(b*5+n)*HW + (size_t)y*1024)[t] = wv;
        float s = (wv.x + wv.y) + (wv.z + wv.w);
        #pragma unroll
        for (int o = 16; o; o >>= 1) s += __shfl_down_sync(0xffffffffu, s, o);
        if (lane == 0) sred[n][wid] = s;
    }
    __syncthreads();
    if (t < 5) {
        float s = 0.f;
        #pragma unroll
        for (int i = 0; i < 8; i++) s += sred[t][i];
        g_wpart[(size_t)(b*5+t)*1024 + y] = s;
    }
}

// ---------------- K3: means + exposure scales (merged) ---------------------------
__global__ void k_statscale() {
    int b = blockIdx.x;     // 4 blocks
    int t = threadIdx.x;    // 256
    __shared__ float red[256];
    __shared__ float Lm[5], wm[5];
    for (int n = 0; n < 5; n++) {
        int bn = b*5 + n;
        float a = (t < 32) ? g_Lpart[bn*32 + t] : 0.f;
        red[t] = a; __syncthreads();
        for (int o = 128; o; o >>= 1) { if (t < o) red[t] += red[t+o]; __syncthreads(); }
        if (t == 0) Lm[n] = fmaxf(red[0] * (1.f/1048576.f), 0.05f);
        __syncthreads();
        float ww = 0.f;
        for (int i = t; i < 1024; i += 256) ww += g_wpart[bn*1024 + i];
        red[t] = ww; __syncthreads();
        for (int o = 128; o; o >>= 1) { if (t < o) red[t] += red[t+o]; __syncthreads(); }
        if (t == 0) wm[n] = red[0] * (1.f/1048576.f);
        __syncthreads();
    }
    if (t == 0) {
        float num = 0.f, den = 1e-6f;
        #pragma unroll
        for (int n = 0; n < 5; n++) { num += Lm[n]*wm[n]; den += wm[n]; }
        float target = num / den;
        #pragma unroll
        for (int n = 0; n < 5; n++) g_scale[b*5+n] = target / Lm[n];
    }
}

// ---------------- K5: fused blur+pool downsample, 64x16 out tile -----------------
__global__ void __launch_bounds__(256) k_down(const float* __restrict__ inA,
                       const float* __restrict__ inB,
                       float* __restrict__ outA, float* __restrict__ outB,
                       int Hi, int Wi, int lvl0) {
    __shared__ float tile[36][132];
    int x0 = blockIdx.x * 64;
    int y0 = blockIdx.y * 16;
    int z = blockIdx.z;
    bool isA = z < NIMG;
    int img = isA ? z : z - NIMG;
    int Ho = Hi >> 1, Wo = Wi >> 1;
    const float* src = (isA ? inA : inB) + (size_t)img * Hi * Wi;
    float* dst = (isA ? outA : outB) + (size_t)img * Ho * Wo;
    bool doclip = lvl0 && isA;
    float sc = doclip ? g_scale[img] : 1.f;
    int t = threadIdx.x;
    for (int idx = t; idx < 36*132; idx += 256) {
        int r = idx / 132, c = idx - r*132;
        int gy = 2*y0 - 2 + r;
        int gx = 2*x0 - 2 + c;
        float v = 0.f;
        if (gy >= 0 && gy < Hi && gx >= 0 && gx < Wi) {
            v = src[(size_t)gy * Wi + gx];
            if (doclip) v = fminf(fmaxf(v * sc, 0.f), 1.f);
        }
        tile[r][c] = v;
    }
    __syncthreads();
    int tx = t & 63, ty = t >> 6;       // ty in 0..3, rows 4*ty .. 4*ty+3
    const float kk[6] = {1.f/32, 5.f/32, 10.f/32, 10.f/32, 5.f/32, 1.f/32};
    // 12 horizontal row-sums shared by the thread's 4 outputs
    float rs[12];
    int c0 = 2*tx;
    #pragma unroll
    for (int rr = 0; rr < 12; rr++) {
        const float* rowp = &tile[8*ty + rr][c0];
        rs[rr] = kk[0]*rowp[0] + kk[1]*rowp[1] + kk[2]*rowp[2]
               + kk[3]*rowp[3] + kk[4]*rowp[4] + kk[5]*rowp[5];
    }
    #pragma unroll
    for (int j = 0; j < 4; j++) {
        float acc = kk[0]*rs[2*j] + kk[1]*rs[2*j+1] + kk[2]*rs[2*j+2]
                  + kk[3]*rs[2*j+3] + kk[4]*rs[2*j+4] + kk[5]*rs[2*j+5];
        dst[(size_t)(y0 + 4*ty + j) * Wo + (x0 + tx)] = acc;
    }
}

// ---------------- bilinear 2x upsample helper ------------------------------------
__device__ __forceinline__ float up1(const float* __restrict__ s, int Hs, int Ws,
                                     int y, int x) {
    int iy = (y - 1) >> 1, ix = (x - 1) >> 1;
    float fy = (y & 1) ? 0.25f : 0.75f;
    float fx = (x & 1) ? 0.25f : 0.75f;
    int y0 = max(iy, 0), y1 = min(iy + 1, Hs - 1);
    int x0 = max(ix, 0), x1 = min(ix + 1, Ws - 1);
    float a = s[(size_t)y0*Ws + x0], b = s[(size_t)y0*Ws + x1];
    float c = s[(size_t)y1*Ws + x0], d = s[(size_t)y1*Ws + x1];
    float top = a + fx*(b - a);
    float bot = c + fx*(d - c);
    return top + fy*(bot - top);
}

// ---------------- K6: 128-level blend with inline P4 (blend4 folded in) ----------
__device__ __forceinline__ float p4at(int b, int j, int i) {
    float s = 1e-6f, a = 0.f;
    #pragma unroll
    for (int n = 0; n < 5; n++) {
        size_t o = (size_t)(b*5+n)*4096 + j*64 + i;
        float gw = g_GW4[o];
        s += gw;
        a += g_GL4[o] * gw;
    }
    return a / s;
}

__global__ void k_blend128() {
    int idx = blockIdx.x*256 + threadIdx.x;
    if (idx >= 4*128*128) return;
    int b = idx >> 14;
    int rem = idx & 16383;
    int y = rem >> 7, x = rem & 127;
    float wv[5]; float qs = 1e-6f;
    #pragma unroll
    for (int n = 0; n < 5; n++) {
        wv[n] = g_GW3[(size_t)(b*5+n)*16384 + rem];
        qs += wv[n];
    }
    float inv = 1.f/qs;
    int iy = (y - 1) >> 1, ix = (x - 1) >> 1;
    float fy = (y & 1) ? 0.25f : 0.75f;
    float fx = (x & 1) ? 0.25f : 0.75f;
    int y0 = max(iy, 0), y1 = min(iy + 1, 63);
    int x0 = max(ix, 0), x1 = min(ix + 1, 63);
    float a = p4at(b, y0, x0), bb = p4at(b, y0, x1);
    float c = p4at(b, y1, x0), d = p4at(b, y1, x1);
    float top = a + fx*(bb - a);
    float bot = c + fx*(d - c);
    float acc = top + fy*(bot - top);
    #pragma unroll
    for (int n = 0; n < 5; n++) {
        float lap = g_GL3[(size_t)(b*5+n)*16384 + rem]
                  - up1(g_GL4 + (size_t)(b*5+n)*4096, 64, 64, y, x);
        acc += lap * wv[n] * inv;
    }
    g_P3[idx] = acc;
}

// ---------------- K7: mid blend, 2 horizontal px per thread ----------------------
__global__ void k_blend2(const float* __restrict__ GL, const float* __restrict__ GLn,
                         const float* __restrict__ GW, const float* __restrict__ pin,
                         float* __restrict__ pout, int H, int W) {
    int idx = blockIdx.x*256 + threadIdx.x;
    int W2 = W >> 1;
    int total = 4*H*W2;
    if (idx >= total) return;
    int b = idx / (H*W2);
    int rem2 = idx - b*(H*W2);
    int y = rem2 / W2, i = rem2 - y*W2;     // output px pair (y, 2i) (y, 2i+1)
    int Hn = H>>1, Wn = W>>1;
    size_t rowoff = (size_t)y*W + 2*i;
    float2 wv[5]; float2 qs = make_float2(1e-6f, 1e-6f);
    #pragma unroll
    for (int n = 0; n < 5; n++) {
        float2 t = *reinterpret_cast<const float2*>(GW + (size_t)(b*5+n)*H*W + rowoff);
        wv[n] = t;
        qs.x += t.x; qs.y += t.y;
    }
    float2 inv = make_float2(1.f/qs.x, 1.f/qs.y);
    int iy = (y - 1) >> 1;
    float fy = (y & 1) ? 0.25f : 0.75f;
    int ry0 = max(iy, 0), ry1 = min(iy + 1, Hn - 1);
    int c0 = max(i - 1, 0);
    int c1 = i;
    int c2 = min(i + 1, Wn - 1);
    float2 acc;
    {
        const float* r0 = pin + (size_t)b*Hn*Wn + (size_t)ry0*Wn;
        const float* r1 = pin + (size_t)b*Hn*Wn + (size_t)ry1*Wn;
        float a0=r0[c0], a1=r0[c1], a2=r0[c2];
        float b0=r1[c0], b1=r1[c1], b2=r1[c2];
        float hx0 = a0 + 0.75f*(a1-a0), hx1 = a1 + 0.25f*(a2-a1);
        float gx0 = b0 + 0.75f*(b1-b0), gx1 = b1 + 0.25f*(b2-b1);
        acc.x = hx0 + fy*(gx0-hx0);
        acc.y = hx1 + fy*(gx1-hx1);
    }
    #pragma unroll
    for (int n = 0; n < 5; n++) {
        float2 gl = *reinterpret_cast<const float2*>(GL + (size_t)(b*5+n)*H*W + rowoff);
        const float* r0 = GLn + (size_t)(b*5+n)*Hn*Wn + (size_t)ry0*Wn;
        const float* r1 = GLn + (size_t)(b*5+n)*Hn*Wn + (size_t)ry1*Wn;
        float a0=r0[c0], a1=r0[c1], a2=r0[c2];
        float b0=r1[c0], b1=r1[c1], b2=r1[c2];
        float hx0 = a0 + 0.75f*(a1-a0), hx1 = a1 + 0.25f*(a2-a1);
        float gx0 = b0 + 0.75f*(b1-b0), gx1 = b1 + 0.25f*(b2-b1);
        float u0 = hx0 + fy*(gx0-hx0);
        float u1 = hx1 + fy*(gx1-hx1);
        acc.x += (gl.x - u0) * wv[n].x * inv.x;
        acc.y += (gl.y - u1) * wv[n].y * inv.y;
    }
    *reinterpret_cast<float2*>(pout + (size_t)b*H*W + rowoff) = acc;
}

// ---------------- K8: final — smem-tiled upsample + lap0 + blend + collapse ------
__global__ void k_final(const float* __restrict__ L, const float* __restrict__ w,
                        float* __restrict__ out) {
    __shared__ float sm[6][6][68];   // planes 0..4 = GL1 n, 5 = P1
    int s  = blockIdx.x;   // col tile (128 out px)
    int tY = blockIdx.y;   // row tile (8 out rows)
    int b  = blockIdx.z;
    int t  = threadIdx.x;
    int cbase = 64*s - 1;
    int rbase = 4*tY - 1;
    for (int idx = t; idx < 6*6*68; idx += 256) {
        int pl = idx / (6*68);
        int rem = idx - pl*6*68;
        int rr = rem / 68, cc = rem - rr*68;
        int rs = min(max(rbase + rr, 0), 511);
        int cs = min(max(cbase + cc, 0), 511);
        float v;
        if (pl < 5) v = g_GL1[((size_t)(b*5+pl)*512 + rs)*512 + cs];
        else        v = g_P1 [((size_t)b*512 + rs)*512 + cs];
        sm[pl][rr][cc] = v;
    }
    __syncthreads();
    int mm = t & 31;
    int r  = t >> 5;
    int y  = 8*tY + r;
    float fy = (r & 1) ? 0.25f : 0.75f;
    int rr0 = ((r - 1) >> 1) + 1;
    int rr1 = rr0 + 1;
    int jc = 2*mm;
    int xo = 128*s + 4*mm;
    size_t po = (size_t)y*1024 + xo;

    float4 acc, u[5];
    {
        #pragma unroll
        for (int pl = 0; pl < 6; pl++) {
            float a0 = sm[pl][rr0][jc],   a1 = sm[pl][rr0][jc+1];
            float a2 = sm[pl][rr0][jc+2], a3 = sm[pl][rr0][jc+3];
            float c0 = sm[pl][rr1][jc],   c1 = sm[pl][rr1][jc+1];
            float c2 = sm[pl][rr1][jc+2], c3 = sm[pl][rr1][jc+3];
            float h0a = a0 + 0.75f*(a1-a0);
            float h1a = a1 + 0.25f*(a2-a1);
            float h2a = a1 + 0.75f*(a2-a1);
            float h3a = a2 + 0.25f*(a3-a2);
            float h0b = c0 + 0.75f*(c1-c0);
            float h1b = c1 + 0.25f*(c2-c1);
            float h2b = c1 + 0.75f*(c2-c1);
            float h3b = c2 + 0.25f*(c3-c2);
            float4 rv;
            rv.x = h0a + fy*(h0b-h0a);
            rv.y = h1a + fy*(h1b-h1a);
            rv.z = h2a + fy*(h2b-h2a);
            rv.w = h3a + fy*(h3b-h3a);
            if (pl < 5) u[pl] = rv; else acc = rv;
        }
    }
    float4 W5[5];
    float4 ws = make_float4(1e-6f, 1e-6f, 1e-6f, 1e-6f);
    #pragma unroll
    for (int n = 0; n < 5; n++) {
        float4 wn = *reinterpret_cast<const float4*>(w + (size_t)(b*5+n)*HW + po);
        W5[n] = wn;
        ws.x += wn.x; ws.y += wn.y; ws.z += wn.z; ws.w += wn.w;
    }
    float4 inv = make_float4(1.f/ws.x, 1.f/ws.y, 1.f/ws.z, 1.f/ws.w);
    #pragma unroll
    for (int n = 0; n < 5; n++) {
        int bn = b*5+n;
        float4 Ln = *reinterpret_cast<const float4*>(L + (size_t)bn*HW + po);
        float scv = g_scale[bn];
        acc.x += (fminf(fmaxf(Ln.x*scv, 0.f), 1.f) - u[n].x) * W5[n].x * inv.x;
        acc.y += (fminf(fmaxf(Ln.y*scv, 0.f), 1.f) - u[n].y) * W5[n].y * inv.y;
        acc.z += (fminf(fmaxf(Ln.z*scv, 0.f), 1.f) - u[n].z) * W5[n].z * inv.z;
        acc.w += (fminf(fmaxf(Ln.w*scv, 0.f), 1.f) - u[n].w) * W5[n].w * inv.w;
    }
    acc.x = fminf(fmaxf(acc.x, 0.f), 1.f);
    acc.y = fminf(fmaxf(acc.y, 0.f), 1.f);
    acc.z = fminf(fmaxf(acc.z, 0.f), 1.f);
    acc.w = fminf(fmaxf(acc.w, 0.f), 1.f);
    *reinterpret_cast<float4*>(out + (size_t)b*HW + po) = acc;
}

// ---------------- launcher -------------------------------------------------------
extern "C" void kernel_launch(void* const* d_in, const int* in_sizes, int n_in,
                              void* d_out, int out_size) {
    const float* L = (const float*)d_in[0];
    float* out = (float*)d_out;
    float* w = out + (size_t)4*HW;

    float *pGL1,*pGL2,*pGL3,*pGL4,*pGW1,*pGW2,*pGW3,*pGW4,*pP1,*pP2,*pP3;
    cudaGetSymbolAddress((void**)&pGL1, g_GL1);
    cudaGetSymbolAddress((void**)&pGL2, g_GL2);
    cudaGetSymbolAddress((void**)&pGL3, g_GL3);
    cudaGetSymbolAddress((void**)&pGL4, g_GL4);
    cudaGetSymbolAddress((void**)&pGW1, g_GW1);
    cudaGetSymbolAddress((void**)&pGW2, g_GW2);
    cudaGetSymbolAddress((void**)&pGW3, g_GW3);
    cudaGetSymbolAddress((void**)&pGW4, g_GW4);
    cudaGetSymbolAddress((void**)&pP1,  g_P1);
    cudaGetSymbolAddress((void**)&pP2,  g_P2);
    cudaGetSymbolAddress((void**)&pP3,  g_P3);

    // quality / weights / stats
    k_hvscan   <<<dim3(32,20), 256>>>(L);
    k_voff     <<<80, 256>>>();
    k_quality  <<<dim3(1024,4), 256>>>(L, w);
    k_statscale<<<4, 256>>>();

    // gaussian pyramids (L with inline scale+clip at level 0; L and w fused, z=40)
    k_down<<<dim3(8,32,40), 256>>>(L,    w,    pGL1, pGW1, 1024, 1024, 1);
    k_down<<<dim3(4,16,40), 256>>>(pGL1, pGW1, pGL2, pGW2,  512,  512, 0);
    k_down<<<dim3(2, 8,40), 256>>>(pGL2, pGW2, pGL3, pGW3,  256,  256, 0);
    k_down<<<dim3(1, 4,40), 256>>>(pGL3, pGW3, pGL4, pGW4,  128,  128, 0);

    // blend + collapse (laplacians inline; top blend folded into 128-level)
    k_blend128<<<(4*128*128+255)/256, 256>>>();
    k_blend2<<<(4*256*128+255)/256, 256>>>(pGL2, pGL3, pGW2, pP3, pP2, 256, 256);
    k_blend2<<<(4*512*256+255)/256, 256>>>(pGL1, pGL2, pGW1, pP2, pP1, 512, 512);
    k_final<<<dim3(8,128,4), 256>>>(L, w, out);
}

// round 11
// speedup vs baseline: 2.8323x; 1.0468x over previous
#include <cuda_runtime.h>

#define HW (1024*1024)
#define NIMG 20

// ---------------- static device scratch ----------------
__device__ float g_S1  [NIMG*HW];        // vertical strip-local prefix of hbox sums
__device__ float g_vp  [NIMG*32*1024];   // per-strip vertical offsets [img][strip][col]
__device__ float g_GL1 [NIMG*512*512];
__device__ float g_GL2 [NIMG*256*256];
__device__ float g_GL3 [NIMG*128*128];
__device__ float g_GL4 [NIMG*64*64];
__device__ float g_GW1 [NIMG*512*512];
__device__ float g_GW2 [NIMG*256*256];
__device__ float g_GW3 [NIMG*128*128];
__device__ float g_GW4 [NIMG*64*64];
__device__ float g_P1  [4*512*512];
__device__ float g_P2  [4*256*256];
__device__ float g_P3  [4*128*128];
__device__ float g_Lpart [NIMG*32];
__device__ float g_wpart [NIMG*1024];
__device__ float g_scale[NIMG];

// ---- K1: fused horizontal box (k=61, row prefix) + vertical strip prefix --------
__global__ void __launch_bounds__(256) k_hvscan(const float* __restrict__ L) {
    int strip = blockIdx.x;            // 0..31
    int img   = blockIdx.y;            // 0..19
    int t = threadIdx.x;
    int lane = t & 31, wid = t >> 5;
    __shared__ float P[2][1024];
    __shared__ float woff[2][8];
    __shared__ float lred[8];
    float v0 = 0.f, v1 = 0.f, v2 = 0.f, v3 = 0.f;   // vertical running sums (4 cols)
    float lacc = 0.f;
    size_t base = ((size_t)img * 1024 + strip * 32) * 1024;
    const float4* src = reinterpret_cast<const float4*>(L + base);
    float4* dst = reinterpret_cast<float4*>(g_S1 + base);

    for (int r = 0; r < 32; r++) {
        int pp = r & 1;
        float4 v = src[r * 256 + t];
        float b0 = fmaxf(v.x - 0.88f, 0.f);
        float b1 = fmaxf(v.y - 0.88f, 0.f);
        float b2 = fmaxf(v.z - 0.88f, 0.f);
        float b3 = fmaxf(v.w - 0.88f, 0.f);
        lacc += (v.x + v.y) + (v.z + v.w);
        float p0 = b0, p1 = p0 + b1, p2 = p1 + b2, p3 = p2 + b3;
        float sc = p3;
        #pragma unroll
        for (int o = 1; o < 32; o <<= 1) {
            float nb = __shfl_up_sync(0xffffffffu, sc, o);
            if (lane >= o) sc += nb;
        }
        if (lane == 31) woff[pp][wid] = sc;
        __syncthreads();
        // redundant per-thread exclusive sum of warp totals below wid (broadcast LDS)
        float bs = sc - p3;
        #pragma unroll
        for (int i = 0; i < 8; i++) {
            float wv = woff[pp][i];
            if (i < wid) bs += wv;
        }
        P[pp][4*t+0] = bs + p0;
        P[pp][4*t+1] = bs + p1;
        P[pp][4*t+2] = bs + p2;
        P[pp][4*t+3] = bs + p3;
        __syncthreads();
        float4 o4;
        {
            int xi = 4*t;
            int hi0 = min(xi + 30, 1023), lo0 = xi - 31;
            float h0 = P[pp][hi0] - (lo0 >= 0 ? P[pp][lo0] : 0.f);
            int hi1 = min(xi + 31, 1023), lo1 = xi - 30;
            float h1 = P[pp][hi1] - (lo1 >= 0 ? P[pp][lo1] : 0.f);
            int hi2 = min(xi + 32, 1023), lo2 = xi - 29;
            float h2 = P[pp][hi2] - (lo2 >= 0 ? P[pp][lo2] : 0.f);
            int hi3 = min(xi + 33, 1023), lo3 = xi - 28;
            float h3 = P[pp][hi3] - (lo3 >= 0 ? P[pp][lo3] : 0.f);
            v0 += h0; v1 += h1; v2 += h2; v3 += h3;
            o4.x = v0; o4.y = v1; o4.z = v2; o4.w = v3;
        }
        dst[r * 256 + t] = o4;
    }
    float4* vpd = reinterpret_cast<float4*>(g_vp + ((size_t)img*32 + strip)*1024);
    float4 tot; tot.x = v0; tot.y = v1; tot.z = v2; tot.w = v3;
    vpd[t] = tot;
    #pragma unroll
    for (int o = 16; o; o >>= 1) lacc += __shfl_down_sync(0xffffffffu, lacc, o);
    if (lane == 0) lred[wid] = lacc;
    __syncthreads();
    if (t == 0) {
        float s = 0.f;
        #pragma unroll
        for (int i = 0; i < 8; i++) s += lred[i];
        g_Lpart[img*32 + strip] = s;
    }
}

// ---------------- K2b: exclusive prefix over 32 strip totals per column ----------
__global__ void k_voff() {
    int idx = blockIdx.x*256 + threadIdx.x;   // 20480
    if (idx >= NIMG*1024) return;
    int img = idx >> 10, col = idx & 1023;
    float* p = g_vp + (size_t)img*32*1024 + col;
    float run = 0.f;
    #pragma unroll
    for (int s = 0; s < 32; s++) { float t = p[s*1024]; p[s*1024] = run; run += t; }
}

// ---------------- K2c: quality + w, float4 per thread ----------------------------
__device__ __forceinline__ float quality1(float Lv, float V) {
    const float cb = -15.f / 3721.f;
    float u = 2.f*Lv - 1.f;
    float t1 = 1.f - u*u;
    float baseq = t1*t1;
    float sat  = __fdividef(1.f, 1.f + __expf( 15.f*(Lv - 0.88f)));
    float dark = __fdividef(1.f, 1.f + __expf(-25.f*(Lv - 0.04f)));
    float bloom = __expf(cb * V);
    return fmaxf(baseq*sat*dark*bloom, 0.02f);
}

__global__ void __launch_bounds__(256) k_quality(const float* __restrict__ L,
                                                 float* __restrict__ wout) {
    int t = threadIdx.x;          // float4 index: 256 * 4 = 1024 px per row
    int y = blockIdx.x;
    int b = blockIdx.y;
    int lane = t & 31, wid = t >> 5;
    int ya = min(y + 30, 1023);
    int yb = y - 31;
    float4 q[5];
    float4 qs = make_float4(1e-6f, 1e-6f, 1e-6f, 1e-6f);
    #pragma unroll
    for (int n = 0; n < 5; n++) {
        int img = b*5 + n;
        const float* Sbase  = g_S1 + (size_t)img*HW;
        const float* vpbase = g_vp + (size_t)img*32*1024;
        float4 Sa = reinterpret_cast<const float4*>(Sbase + (size_t)ya*1024)[t];
        float4 va = reinterpret_cast<const float4*>(vpbase + (ya>>5)*1024)[t];
        float4 V;
        V.x = Sa.x + va.x; V.y = Sa.y + va.y; V.z = Sa.z + va.z; V.w = Sa.w + va.w;
        if (yb >= 0) {
            float4 Sb = reinterpret_cast<const float4*>(Sbase + (size_t)yb*1024)[t];
            float4 vb = reinterpret_cast<const float4*>(vpbase + (yb>>5)*1024)[t];
            V.x -= Sb.x + vb.x; V.y -= Sb.y + vb.y; V.z -= Sb.z + vb.z; V.w -= Sb.w + vb.w;
        }
        float4 Lv = reinterpret_cast<const float4*>(L + (size_t)img*HW + (size_t)y*1024)[t];
        float4 qn;
        qn.x = quality1(Lv.x, V.x);
        qn.y = quality1(Lv.y, V.y);
        qn.z = quality1(Lv.z, V.z);
        qn.w = quality1(Lv.w, V.w);
        q[n] = qn;
        qs.x += qn.x; qs.y += qn.y; qs.z += qn.z; qs.w += qn.w;
    }
    float4 inv;
    inv.x = __fdividef(1.f, qs.x); inv.y = __fdividef(1.f, qs.y);
    inv.z = __fdividef(1.f, qs.z); inv.w = __fdividef(1.f, qs.w);
    __shared__ float sred[5][8];
    #pragma unroll
    for (int n = 0; n < 5; n++) {
        float4 wv;
        wv.x = q[n].x*inv.x; wv.y = q[n].y*inv.y;
        wv.z = q[n].z*inv.z; wv.w = q[n].w*inv.w;
        reinterpret_cast<float4*>(wout + (size_t)(b*5+n)*HW + (size_t)y*1024)[t] = wv;
        float s = (wv.x + wv.y) + (wv.z + wv.w);
        #pragma unroll
        for (int o = 16; o; o >>= 1) s += __shfl_down_sync(0xffffffffu, s, o);
        if (lane == 0) sred[n][wid] = s;
    }
    __syncthreads();
    if (t < 5) {
        float s = 0.f;
        #pragma unroll
        for (int i = 0; i < 8; i++) s += sred[t][i];
        g_wpart[(size_t)(b*5+t)*1024 + y] = s;
    }
}

// ---------------- K3: means + exposure scales (parallel 10-wide reduction) -------
__global__ void __launch_bounds__(256) k_statscale() {
    int b = blockIdx.x;     // 4 blocks
    int t = threadIdx.x;    // 256
    __shared__ float red[10][264];   // padded stride kills tree-reduction conflicts
    #pragma unroll
    for (int n = 0; n < 5; n++) {
        int bn = b*5 + n;
        float a = 0.f;
        for (int i = t; i < 1024; i += 256) a += g_wpart[bn*1024 + i];
        red[n][t] = a;
        red[5+n][t] = (t < 32) ? g_Lpart[bn*32 + t] : 0.f;
    }
    __syncthreads();
    for (int o = 128; o; o >>= 1) {
        if (t < o) {
            #pragma unroll
            for (int k = 0; k < 10; k++) red[k][t] += red[k][t+o];
        }
        __syncthreads();
    }
    if (t == 0) {
        float num = 0.f, den = 1e-6f;
        float Lm[5], wm[5];
        #pragma unroll
        for (int n = 0; n < 5; n++) {
            wm[n] = red[n][0] * (1.f/1048576.f);
            Lm[n] = fmaxf(red[5+n][0] * (1.f/1048576.f), 0.05f);
            num += Lm[n]*wm[n]; den += wm[n];
        }
        float target = num / den;
        #pragma unroll
        for (int n = 0; n < 5; n++) g_scale[b*5+n] = target / Lm[n];
    }
}

// ---------------- K5: fused blur+pool downsample, 64x16 out tile -----------------
__global__ void __launch_bounds__(256) k_down(const float* __restrict__ inA,
                       const float* __restrict__ inB,
                       float* __restrict__ outA, float* __restrict__ outB,
                       int Hi, int Wi, int lvl0) {
    __shared__ float tile[36][132];
    int x0 = blockIdx.x * 64;
    int y0 = blockIdx.y * 16;
    int z = blockIdx.z;
    bool isA = z < NIMG;
    int img = isA ? z : z - NIMG;
    int Ho = Hi >> 1, Wo = Wi >> 1;
    const float* src = (isA ? inA : inB) + (size_t)img * Hi * Wi;
    float* dst = (isA ? outA : outB) + (size_t)img * Ho * Wo;
    bool doclip = lvl0 && isA;
    float sc = doclip ? g_scale[img] : 1.f;
    int t = threadIdx.x;
    for (int idx = t; idx < 36*132; idx += 256) {
        int r = idx / 132, c = idx - r*132;
        int gy = 2*y0 - 2 + r;
        int gx = 2*x0 - 2 + c;
        float v = 0.f;
        if (gy >= 0 && gy < Hi && gx >= 0 && gx < Wi) {
            v = src[(size_t)gy * Wi + gx];
            if (doclip) v = fminf(fmaxf(v * sc, 0.f), 1.f);
        }
        tile[r][c] = v;
    }
    __syncthreads();
    int tx = t & 63, ty = t >> 6;       // ty in 0..3, rows 4*ty .. 4*ty+3
    const float kk[6] = {1.f/32, 5.f/32, 10.f/32, 10.f/32, 5.f/32, 1.f/32};
    float rs[12];
    int c0 = 2*tx;
    #pragma unroll
    for (int rr = 0; rr < 12; rr++) {
        const float* rowp = &tile[8*ty + rr][c0];
        rs[rr] = kk[0]*rowp[0] + kk[1]*rowp[1] + kk[2]*rowp[2]
               + kk[3]*rowp[3] + kk[4]*rowp[4] + kk[5]*rowp[5];
    }
    #pragma unroll
    for (int j = 0; j < 4; j++) {
        float acc = kk[0]*rs[2*j] + kk[1]*rs[2*j+1] + kk[2]*rs[2*j+2]
                  + kk[3]*rs[2*j+3] + kk[4]*rs[2*j+4] + kk[5]*rs[2*j+5];
        dst[(size_t)(y0 + 4*ty + j) * Wo + (x0 + tx)] = acc;
    }
}

// ---------------- bilinear 2x upsample helper ------------------------------------
__device__ __forceinline__ float up1(const float* __restrict__ s, int Hs, int Ws,
                                     int y, int x) {
    int iy = (y - 1) >> 1, ix = (x - 1) >> 1;
    float fy = (y & 1) ? 0.25f : 0.75f;
    float fx = (x & 1) ? 0.25f : 0.75f;
    int y0 = max(iy, 0), y1 = min(iy + 1, Hs - 1);
    int x0 = max(ix, 0), x1 = min(ix + 1, Ws - 1);
    float a = s[(size_t)y0*Ws + x0], b = s[(size_t)y0*Ws + x1];
    float c = s[(size_t)y1*Ws + x0], d = s[(size_t)y1*Ws + x1];
    float top = a + fx*(b - a);
    float bot = c + fx*(d - c);
    return top + fy*(bot - top);
}

// ---------------- K6: 128-level blend with inline P4 (blend4 folded in) ----------
__device__ __forceinline__ float p4at(int b, int j, int i) {
    float s = 1e-6f, a = 0.f;
    #pragma unroll
    for (int n = 0; n < 5; n++) {
        size_t o = (size_t)(b*5+n)*4096 + j*64 + i;
        float gw = g_GW4[o];
        s += gw;
        a += g_GL4[o] * gw;
    }
    return __fdividef(a, s);
}

__global__ void k_blend128() {
    int idx = blockIdx.x*256 + threadIdx.x;
    if (idx >= 4*128*128) return;
    int b = idx >> 14;
    int rem = idx & 16383;
    int y = rem >> 7, x = rem & 127;
    float wv[5]; float qs = 1e-6f;
    #pragma unroll
    for (int n = 0; n < 5; n++) {
        wv[n] = g_GW3[(size_t)(b*5+n)*16384 + rem];
        qs += wv[n];
    }
    float inv = __fdividef(1.f, qs);
    int iy = (y - 1) >> 1, ix = (x - 1) >> 1;
    float fy = (y & 1) ? 0.25f : 0.75f;
    float fx = (x & 1) ? 0.25f : 0.75f;
    int y0 = max(iy, 0), y1 = min(iy + 1, 63);
    int x0 = max(ix, 0), x1 = min(ix + 1, 63);
    float a = p4at(b, y0, x0), bb = p4at(b, y0, x1);
    float c = p4at(b, y1, x0), d = p4at(b, y1, x1);
    float top = a + fx*(bb - a);
    float bot = c + fx*(d - c);
    float acc = top + fy*(bot - top);
    #pragma unroll
    for (int n = 0; n < 5; n++) {
        float lap = g_GL3[(size_t)(b*5+n)*16384 + rem]
                  - up1(g_GL4 + (size_t)(b*5+n)*4096, 64, 64, y, x);
        acc += lap * wv[n] * inv;
    }
    g_P3[idx] = acc;
}

// ---------------- K7: mid blend, 2 horizontal px per thread ----------------------
__global__ void k_blend2(const float* __restrict__ GL, const float* __restrict__ GLn,
                         const float* __restrict__ GW, const float* __restrict__ pin,
                         float* __restrict__ pout, int H, int W) {
    int idx = blockIdx.x*256 + threadIdx.x;
    int W2 = W >> 1;
    int total = 4*H*W2;
    if (idx >= total) return;
    int b = idx / (H*W2);
    int rem2 = idx - b*(H*W2);
    int y = rem2 / W2, i = rem2 - y*W2;     // output px pair (y, 2i) (y, 2i+1)
    int Hn = H>>1, Wn = W>>1;
    size_t rowoff = (size_t)y*W + 2*i;
    float2 wv[5]; float2 qs = make_float2(1e-6f, 1e-6f);
    #pragma unroll
    for (int n = 0; n < 5; n++) {
        float2 t = *reinterpret_cast<const float2*>(GW + (size_t)(b*5+n)*H*W + rowoff);
        wv[n] = t;
        qs.x += t.x; qs.y += t.y;
    }
    float2 inv = make_float2(__fdividef(1.f, qs.x), __fdividef(1.f, qs.y));
    int iy = (y - 1) >> 1;
    float fy = (y & 1) ? 0.25f : 0.75f;
    int ry0 = max(iy, 0), ry1 = min(iy + 1, Hn - 1);
    int c0 = max(i - 1, 0);
    int c1 = i;
    int c2 = min(i + 1, Wn - 1);
    float2 acc;
    {
        const float* r0 = pin + (size_t)b*Hn*Wn + (size_t)ry0*Wn;
        const float* r1 = pin + (size_t)b*Hn*Wn + (size_t)ry1*Wn;
        float a0=r0[c0], a1=r0[c1], a2=r0[c2];
        float b0=r1[c0], b1=r1[c1], b2=r1[c2];
        float hx0 = a0 + 0.75f*(a1-a0), hx1 = a1 + 0.25f*(a2-a1);
        float gx0 = b0 + 0.75f*(b1-b0), gx1 = b1 + 0.25f*(b2-b1);
        acc.x = hx0 + fy*(gx0-hx0);
        acc.y = hx1 + fy*(gx1-hx1);
    }
    #pragma unroll
    for (int n = 0; n < 5; n++) {
        float2 gl = *reinterpret_cast<const float2*>(GL + (size_t)(b*5+n)*H*W + rowoff);
        const float* r0 = GLn + (size_t)(b*5+n)*Hn*Wn + (size_t)ry0*Wn;
        const float* r1 = GLn + (size_t)(b*5+n)*Hn*Wn + (size_t)ry1*Wn;
        float a0=r0[c0], a1=r0[c1], a2=r0[c2];
        float b0=r1[c0], b1=r1[c1], b2=r1[c2];
        float hx0 = a0 + 0.75f*(a1-a0), hx1 = a1 + 0.25f*(a2-a1);
        float gx0 = b0 + 0.75f*(b1-b0), gx1 = b1 + 0.25f*(b2-b1);
        float u0 = hx0 + fy*(gx0-hx0);
        float u1 = hx1 + fy*(gx1-hx1);
        acc.x += (gl.x - u0) * wv[n].x * inv.x;
        acc.y += (gl.y - u1) * wv[n].y * inv.y;
    }
    *reinterpret_cast<float2*>(pout + (size_t)b*H*W + rowoff) = acc;
}

// ---------------- K8: final — smem-tiled upsample + lap0 + blend + collapse ------
__global__ void k_final(const float* __restrict__ L, const float* __restrict__ w,
                        float* __restrict__ out) {
    __shared__ float sm[6][6][68];   // planes 0..4 = GL1 n, 5 = P1
    int s  = blockIdx.x;   // col tile (128 out px)
    int tY = blockIdx.y;   // row tile (8 out rows)
    int b  = blockIdx.z;
    int t  = threadIdx.x;
    int cbase = 64*s - 1;
    int rbase = 4*tY - 1;
    for (int idx = t; idx < 6*6*68; idx += 256) {
        int pl = idx / (6*68);
        int rem = idx - pl*6*68;
        int rr = rem / 68, cc = rem - rr*68;
        int rs = min(max(rbase + rr, 0), 511);
        int cs = min(max(cbase + cc, 0), 511);
        float v;
        if (pl < 5) v = g_GL1[((size_t)(b*5+pl)*512 + rs)*512 + cs];
        else        v = g_P1 [((size_t)b*512 + rs)*512 + cs];
        sm[pl][rr][cc] = v;
    }
    __syncthreads();
    int mm = t & 31;
    int r  = t >> 5;
    int y  = 8*tY + r;
    float fy = (r & 1) ? 0.25f : 0.75f;
    int rr0 = ((r - 1) >> 1) + 1;
    int rr1 = rr0 + 1;
    int jc = 2*mm;
    int xo = 128*s + 4*mm;
    size_t po = (size_t)y*1024 + xo;

    float4 acc, u[5];
    {
        #pragma unroll
        for (int pl = 0; pl < 6; pl++) {
            float a0 = sm[pl][rr0][jc],   a1 = sm[pl][rr0][jc+1];
            float a2 = sm[pl][rr0][jc+2], a3 = sm[pl][rr0][jc+3];
            float c0 = sm[pl][rr1][jc],   c1 = sm[pl][rr1][jc+1];
            float c2 = sm[pl][rr1][jc+2], c3 = sm[pl][rr1][jc+3];
            float h0a = a0 + 0.75f*(a1-a0);
            float h1a = a1 + 0.25f*(a2-a1);
            float h2a = a1 + 0.75f*(a2-a1);
            float h3a = a2 + 0.25f*(a3-a2);
            float h0b = c0 + 0.75f*(c1-c0);
            float h1b = c1 + 0.25f*(c2-c1);
            float h2b = c1 + 0.75f*(c2-c1);
            float h3b = c2 + 0.25f*(c3-c2);
            float4 rv;
            rv.x = h0a + fy*(h0b-h0a);
            rv.y = h1a + fy*(h1b-h1a);
            rv.z = h2a + fy*(h2b-h2a);
            rv.w = h3a + fy*(h3b-h3a);
            if (pl < 5) u[pl] = rv; else acc = rv;
        }
    }
    float4 W5[5];
    float4 ws = make_float4(1e-6f, 1e-6f, 1e-6f, 1e-6f);
    #pragma unroll
    for (int n = 0; n < 5; n++) {
        float4 wn = *reinterpret_cast<const float4*>(w + (size_t)(b*5+n)*HW + po);
        W5[n] = wn;
        ws.x += wn.x; ws.y += wn.y; ws.z += wn.z; ws.w += wn.w;
    }
    float4 inv;
    inv.x = __fdividef(1.f, ws.x); inv.y = __fdividef(1.f, ws.y);
    inv.z = __fdividef(1.f, ws.z); inv.w = __fdividef(1.f, ws.w);
    #pragma unroll
    for (int n = 0; n < 5; n++) {
        int bn = b*5+n;
        float4 Ln = *reinterpret_cast<const float4*>(L + (size_t)bn*HW + po);
        float scv = g_scale[bn];
        acc.x += (fminf(fmaxf(Ln.x*scv, 0.f), 1.f) - u[n].x) * W5[n].x * inv.x;
        acc.y += (fminf(fmaxf(Ln.y*scv, 0.f), 1.f) - u[n].y) * W5[n].y * inv.y;
        acc.z += (fminf(fmaxf(Ln.z*scv, 0.f), 1.f) - u[n].z) * W5[n].z * inv.z;
        acc.w += (fminf(fmaxf(Ln.w*scv, 0.f), 1.f) - u[n].w) * W5[n].w * inv.w;
    }
    acc.x = fminf(fmaxf(acc.x, 0.f), 1.f);
    acc.y = fminf(fmaxf(acc.y, 0.f), 1.f);
    acc.z = fminf(fmaxf(acc.z, 0.f), 1.f);
    acc.w = fminf(fmaxf(acc.w, 0.f), 1.f);
    *reinterpret_cast<float4*>(out + (size_t)b*HW + po) = acc;
}

// ---------------- launcher -------------------------------------------------------
extern "C" void kernel_launch(void* const* d_in, const int* in_sizes, int n_in,
                              void* d_out, int out_size) {
    const float* L = (const float*)d_in[0];
    float* out = (float*)d_out;
    float* w = out + (size_t)4*HW;

    float *pGL1,*pGL2,*pGL3,*pGL4,*pGW1,*pGW2,*pGW3,*pGW4,*pP1,*pP2,*pP3;
    cudaGetSymbolAddress((void**)&pGL1, g_GL1);
    cudaGetSymbolAddress((void**)&pGL2, g_GL2);
    cudaGetSymbolAddress((void**)&pGL3, g_GL3);
    cudaGetSymbolAddress((void**)&pGL4, g_GL4);
    cudaGetSymbolAddress((void**)&pGW1, g_GW1);
    cudaGetSymbolAddress((void**)&pGW2, g_GW2);
    cudaGetSymbolAddress((void**)&pGW3, g_GW3);
    cudaGetSymbolAddress((void**)&pGW4, g_GW4);
    cudaGetSymbolAddress((void**)&pP1,  g_P1);
    cudaGetSymbolAddress((void**)&pP2,  g_P2);
    cudaGetSymbolAddress((void**)&pP3,  g_P3);

    // quality / weights / stats
    k_hvscan   <<<dim3(32,20), 256>>>(L);
    k_voff     <<<80, 256>>>();
    k_quality  <<<dim3(1024,4), 256>>>(L, w);
    k_statscale<<<4, 256>>>();

    // gaussian pyramids (L with inline scale+clip at level 0; L and w fused, z=40)
    k_down<<<dim3(8,32,40), 256>>>(L,    w,    pGL1, pGW1, 1024, 1024, 1);
    k_down<<<dim3(4,16,40), 256>>>(pGL1, pGW1, pGL2, pGW2,  512,  512, 0);
    k_down<<<dim3(2, 8,40), 256>>>(pGL2, pGW2, pGL3, pGW3,  256,  256, 0);
    k_down<<<dim3(1, 4,40), 256>>>(pGL3, pGW3, pGL4, pGW4,  128,  128, 0);

    // blend + collapse (laplacians inline; top blend folded into 128-level)
    k_blend128<<<(4*128*128+255)/256, 256>>>();
    k_blend2<<<(4*256*128+255)/256, 256>>>(pGL2, pGL3, pGW2, pP3, pP2, 256, 256);
    k_blend2<<<(4*512*256+255)/256, 256>>>(pGL1, pGL2, pGW1, pP2, pP1, 512, 512);
    k_final<<<dim3(8,128,4), 256>>>(L, w, out);
}